// round 4
// baseline (speedup 1.0000x reference)
#include <cuda_runtime.h>
#include <cstddef>

#define N_AQI 35
#define N_MEO 18
#define NTOT  53
#define F_OUT 64
#define CTXD  60
#define BATCH 4096
#define NEGV  (-1e12f)
#define LALPHA 0.2f

// layout strides
#define PXT_STRIDE 60     // projxT[feat][node]
#define WT_STRIDE  20     // WT[feat][k]
#define ATT_STRIDE 56
#define FULL_STRIDE 28    // unified full-feature rows (conflict-free float4 per lane)

// ---------------- batch-independent precomputed state ----------------
__device__ float g_bias[NTOT * NTOT];
__device__ unsigned int g_mask[NTOT][2];
__device__ __align__(16) float g_wsrc[2][2][FULL_STRIDE];
__device__ __align__(16) float g_wdst[2][2][FULL_STRIDE];
__device__ __align__(16) float g_WxaT[64 * WT_STRIDE];
__device__ __align__(16) float g_WxmT[64 * WT_STRIDE];

__global__ void precompute_kernel(
    const float* __restrict__ ctx,
    const float* __restrict__ adj_norm,
    const float* __restrict__ a_aa, const float* __restrict__ a_am,
    const float* __restrict__ a_ma, const float* __restrict__ a_mm,
    const float* __restrict__ W_ua, const float* __restrict__ W_um,
    const float* __restrict__ W_xa, const float* __restrict__ W_xm,
    const int*   __restrict__ adj)
{
    __shared__ float s_cs[NTOT][2];
    __shared__ float s_ct[NTOT][2];
    const int tid = threadIdx.x;
    const float* A[2][2] = {{a_aa, a_am}, {a_ma, a_mm}};

    for (int id = tid; id < NTOT * 4; id += blockDim.x) {
        int i = id % NTOT;
        int sel = id / NTOT;
        if (sel < 2) {
            int rb = (i < N_AQI) ? 0 : 1;
            const float* a = A[rb][sel];
            float acc = 0.f;
            for (int c = 0; c < CTXD; c++) acc += ctx[i * CTXD + c] * a[64 + c];
            s_cs[i][sel] = acc;
        } else {
            int rb = sel - 2;
            int cb = (i < N_AQI) ? 0 : 1;
            const float* a = A[rb][cb];
            float acc = 0.f;
            for (int c = 0; c < CTXD; c++) acc += ctx[i * CTXD + c] * a[188 + c];
            s_ct[i][rb] = acc;
        }
    }

    for (int id = tid; id < 2 * 2 * 2 * FULL_STRIDE; id += blockDim.x) {
        int k = id % FULL_STRIDE;
        int r = id / FULL_STRIDE;
        int which = r >> 2;
        int t0 = (r >> 1) & 1;
        int t1 = r & 1;
        const float* W = (t0 == 0) ? W_ua : W_um;
        int K = (t0 == 0) ? 24 : 26;
        float acc = 0.f;
        if (k < K) {
            const float* a = (which == 0) ? A[t0][t1] : A[t1][t0];
            int off = (which == 0) ? 0 : 124;
            for (int f = 0; f < 64; f++) acc += W[k * 64 + f] * a[off + f];
        }
        if (which == 0) g_wsrc[t0][t1][k] = acc;
        else            g_wdst[t0][t1][k] = acc;
    }

    for (int id = tid; id < 64 * WT_STRIDE; id += blockDim.x) {
        int f = id / WT_STRIDE, k = id % WT_STRIDE;
        g_WxaT[id] = (k < 16) ? W_xa[k * 64 + f] : 0.f;
        g_WxmT[id] = (k < 16) ? W_xm[k * 64 + f] : 0.f;
    }

    for (int i = tid; i < NTOT; i += blockDim.x) {
        unsigned int m0 = 0, m1 = 0;
        for (int j = 0; j < 32; j++)   if (adj[i * NTOT + j] > 0) m0 |= (1u << j);
        for (int j = 32; j < NTOT; j++) if (adj[i * NTOT + j] > 0) m1 |= (1u << (j - 32));
        g_mask[i][0] = m0; g_mask[i][1] = m1;
    }
    __syncthreads();

    for (int id = tid; id < NTOT * NTOT; id += blockDim.x) {
        int i = id / NTOT, j = id % NTOT;
        int rb = (i < N_AQI) ? 0 : 1;
        int cb = (j < N_AQI) ? 0 : 1;
        g_bias[id] = s_cs[i][cb] + s_ct[j][rb] + adj_norm[id] * A[rb][cb][248];
    }
}

// ---------------- packed fp32 helpers (sm_103a f32x2) ----------------
__device__ __forceinline__ unsigned long long fma2(unsigned long long a,
                                                   unsigned long long b,
                                                   unsigned long long c)
{
    unsigned long long d;
    asm("fma.rn.f32x2 %0, %1, %2, %3;" : "=l"(d) : "l"(a), "l"(b), "l"(c));
    return d;
}
__device__ __forceinline__ float lo32(unsigned long long v) { return __uint_as_float((unsigned)v); }
__device__ __forceinline__ float hi32(unsigned long long v) { return __uint_as_float((unsigned)(v >> 32)); }

// ---------------- main kernel: one CTA per batch element ----------------
__global__ __launch_bounds__(256, 4) void hgat_kernel(
    const float* __restrict__ aqi_inp, const float* __restrict__ meo_inp,
    const float* __restrict__ aqi_idE, const float* __restrict__ aqi_monthE,
    const float* __restrict__ aqi_weekdayE, const float* __restrict__ aqi_hourE,
    const float* __restrict__ meo_windE, const float* __restrict__ meo_idE,
    const float* __restrict__ meo_monthE, const float* __restrict__ meo_weekdayE,
    const float* __restrict__ meo_hourE,
    const int* __restrict__ aqi_ex, const int* __restrict__ meo_ex,
    float* __restrict__ out)
{
    __shared__ float s_full[56 * FULL_STRIDE];
    __shared__ float s_WxaT[64 * WT_STRIDE];
    __shared__ float s_WxmT[64 * WT_STRIDE];
    __shared__ float s_projxT[64 * PXT_STRIDE];
    __shared__ float s_attn[56 * ATT_STRIDE];
    __shared__ float s_S[NTOT * 2];
    __shared__ float s_T[NTOT * 2];

    const int tid = threadIdx.x;
    const int b = blockIdx.x;

    // ---- Phase 0: stage weights (float4 memcpy), gather rows, zero pads ----
    {
        const float4* sa = reinterpret_cast<const float4*>(g_WxaT);
        const float4* sm = reinterpret_cast<const float4*>(g_WxmT);
        float4* da = reinterpret_cast<float4*>(s_WxaT);
        float4* dm = reinterpret_cast<float4*>(s_WxmT);
        #pragma unroll
        for (int it = 0; it < 2; it++) {
            int i = tid + it * 256;
            if (i < 320) { da[i] = sa[i]; dm[i] = sm[i]; }
        }
    }
    // zero pads: projxT cols 53-55 (all feats); attn cols 53-55 (all 56 rows);
    // attn rows 53-55 cols 0-52 (these rows are now multiplied into discarded accs
    // in phase 4 and must be finite).
    if (tid < 192) {
        int f = tid / 3, c = 53 + tid % 3;
        s_projxT[f * PXT_STRIDE + c] = 0.f;
    }
    for (int z = tid; z < 56 * 3; z += 256)
        s_attn[(z / 3) * ATT_STRIDE + 53 + (z % 3)] = 0.f;
    for (int z = tid; z < 3 * 53; z += 256)
        s_attn[(53 + z / 53) * ATT_STRIDE + (z % 53)] = 0.f;

    for (int id = tid; id < N_AQI * FULL_STRIDE; id += 256) {
        int i = id / FULL_STRIDE, c = id % FULL_STRIDE;
        float v = 0.f;
        if (c < 16) v = aqi_inp[((size_t)b * N_AQI + i) * 16 + c];
        else if (c < 24) {
            int e = (c - 16) >> 1, comp = (c - 16) & 1;
            int ix = aqi_ex[((size_t)b * N_AQI + i) * 4 + e];
            const float* tab = (e == 0) ? aqi_idE : (e == 1) ? aqi_monthE
                             : (e == 2) ? aqi_weekdayE : aqi_hourE;
            v = tab[ix * 2 + comp];
        }
        s_full[i * FULL_STRIDE + c] = v;
    }
    for (int id = tid; id < N_MEO * FULL_STRIDE; id += 256) {
        int i = id / FULL_STRIDE, c = id % FULL_STRIDE;
        float v = 0.f;
        if (c < 16) v = meo_inp[((size_t)b * N_MEO + i) * 16 + c];
        else if (c < 26) {
            int e = (c - 16) >> 1, comp = (c - 16) & 1;
            int ix = meo_ex[((size_t)b * N_MEO + i) * 5 + e];
            const float* tab = (e == 0) ? meo_windE : (e == 1) ? meo_idE
                             : (e == 2) ? meo_monthE : (e == 3) ? meo_weekdayE : meo_hourE;
            v = tab[ix * 2 + comp];
        }
        s_full[(N_AQI + i) * FULL_STRIDE + c] = v;
    }
    __syncthreads();

    // ---- Phase 1: projxT = (full @ W_x)^T, packed f32x2 over k-pairs ----
    {
        const int f = tid & 63, rg = tid >> 6;
        const float* wta = &s_WxaT[f * WT_STRIDE];
        const float* wtm = &s_WxmT[f * WT_STRIDE];

        unsigned long long accA[9];
        #pragma unroll
        for (int r = 0; r < 9; r++) accA[r] = 0ull;
        #pragma unroll
        for (int kg = 0; kg < 4; kg++) {
            ulonglong2 wv = *reinterpret_cast<const ulonglong2*>(wta + 4 * kg);
            #pragma unroll
            for (int r = 0; r < 9; r++) {
                int n = rg + 4 * r;
                ulonglong2 xv = *reinterpret_cast<const ulonglong2*>(&s_full[n * FULL_STRIDE + 4 * kg]);
                accA[r] = fma2(wv.x, xv.x, accA[r]);
                accA[r] = fma2(wv.y, xv.y, accA[r]);
            }
        }
        #pragma unroll
        for (int r = 0; r < 9; r++) {
            int n = rg + 4 * r;
            if (n < N_AQI) s_projxT[f * PXT_STRIDE + n] = lo32(accA[r]) + hi32(accA[r]);
        }

        unsigned long long accM[5];
        #pragma unroll
        for (int r = 0; r < 5; r++) accM[r] = 0ull;
        #pragma unroll
        for (int kg = 0; kg < 4; kg++) {
            ulonglong2 wv = *reinterpret_cast<const ulonglong2*>(wtm + 4 * kg);
            #pragma unroll
            for (int r = 0; r < 5; r++) {
                int n = rg + 4 * r;
                ulonglong2 xv = *reinterpret_cast<const ulonglong2*>(&s_full[(N_AQI + n) * FULL_STRIDE + 4 * kg]);
                accM[r] = fma2(wv.x, xv.x, accM[r]);
                accM[r] = fma2(wv.y, xv.y, accM[r]);
            }
        }
        #pragma unroll
        for (int r = 0; r < 5; r++) {
            int n = rg + 4 * r;
            if (n < N_MEO) s_projxT[f * PXT_STRIDE + N_AQI + n] = lo32(accM[r]) + hi32(accM[r]);
        }
    }

    // ---- Phase 2: S[i][cb], T[j][rb] via folded vectors, float4 dots ----
    if (tid < NTOT * 4) {
        int i = tid % NTOT;
        int sel = tid / NTOT;
        int rt = (i < N_AQI) ? 0 : 1;
        const float4* xr = reinterpret_cast<const float4*>(&s_full[i * FULL_STRIDE]);
        const float4* wv = reinterpret_cast<const float4*>(
            (sel < 2) ? g_wsrc[rt][sel] : g_wdst[rt][sel - 2]);
        float acc = 0.f;
        #pragma unroll
        for (int m = 0; m < 7; m++) {
            float4 x = xr[m], w = wv[m];
            acc += x.x * w.x + x.y * w.y + x.z * w.z + x.w * w.w;
        }
        if (sel < 2) s_S[i * 2 + sel] = acc;
        else         s_T[i * 2 + (sel - 2)] = acc;
    }
    __syncthreads();

    // ---- Phase 3: masked leaky-relu scores + softmax, one warp per row ----
    {
        const int w = tid >> 5, lane = tid & 31;
        const int j1 = lane, j2 = lane + 32;
        const int cb1 = (j1 < N_AQI) ? 0 : 1;
        const int cb2 = (j2 < N_AQI) ? 0 : 1;
        const float t1_0 = s_T[j1 * 2 + 0], t1_1 = s_T[j1 * 2 + 1];
        const bool v2 = (j2 < NTOT);
        const float t2_0 = v2 ? s_T[j2 * 2 + 0] : 0.f;
        const float t2_1 = v2 ? s_T[j2 * 2 + 1] : 0.f;

        for (int i = w; i < NTOT; i += 8) {
            const int rb = (i < N_AQI) ? 0 : 1;
            const unsigned int m0 = g_mask[i][0], m1 = g_mask[i][1];
            float e1, e2;
            {
                float v = s_S[i * 2 + cb1] + (rb ? t1_1 : t1_0) + g_bias[i * NTOT + j1];
                v = (v >= 0.f) ? v : LALPHA * v;
                e1 = ((m0 >> j1) & 1u) ? v : NEGV;
            }
            if (v2) {
                float v = s_S[i * 2 + cb2] + (rb ? t2_1 : t2_0) + g_bias[i * NTOT + j2];
                v = (v >= 0.f) ? v : LALPHA * v;
                e2 = ((m1 >> (j2 - 32)) & 1u) ? v : NEGV;
            } else {
                e2 = -3.4e38f;
            }
            float mx = fmaxf(e1, e2);
            #pragma unroll
            for (int o = 16; o > 0; o >>= 1) mx = fmaxf(mx, __shfl_xor_sync(0xffffffffu, mx, o));
            float p1 = __expf(e1 - mx);
            float p2 = v2 ? __expf(e2 - mx) : 0.f;
            float sum = p1 + p2;
            #pragma unroll
            for (int o = 16; o > 0; o >>= 1) sum += __shfl_xor_sync(0xffffffffu, sum, o);
            float inv = 1.f / sum;
            s_attn[i * ATT_STRIDE + j1] = p1 * inv;
            if (v2) s_attn[i * ATT_STRIDE + j2] = p2 * inv;
        }
    }
    __syncthreads();

    // ---- Phase 4: out = attn @ proj_x, 2D warp tiling (28 rows x 16 feats) ----
    // warp = (rt row-tile, ft feat-tile); lane = (rl in 0..3 rows, fl in 0..7 feats).
    // px load: 8 distinct addrs x 4-lane multicast = 128B = 1 wavefront.
    // attn load: 4 distinct addrs x 8-lane multicast = 64B = 1 wavefront.
    {
        const int w = tid >> 5, lane = tid & 31;
        const int fl = lane & 7, rl = lane >> 3;
        const int ft = w & 3, rt = w >> 2;
        const int F0 = ft * 16 + fl;           // this lane's feats: F0, F0+8
        const int I0 = rt * 28 + rl;           // this lane's rows: I0 + 4r
        const float* px0p = &s_projxT[F0 * PXT_STRIDE];
        const float* px1p = &s_projxT[(F0 + 8) * PXT_STRIDE];
        const float* atp  = &s_attn[I0 * ATT_STRIDE];

        unsigned long long acc0[7], acc1[7];
        #pragma unroll
        for (int r = 0; r < 7; r++) { acc0[r] = 0ull; acc1[r] = 0ull; }

        #pragma unroll 2
        for (int g = 0; g < 14; g++) {
            ulonglong2 px0 = *reinterpret_cast<const ulonglong2*>(px0p + 4 * g);
            ulonglong2 px1 = *reinterpret_cast<const ulonglong2*>(px1p + 4 * g);
            #pragma unroll
            for (int r = 0; r < 7; r++) {
                ulonglong2 at = *reinterpret_cast<const ulonglong2*>(
                    atp + (4 * r) * ATT_STRIDE + 4 * g);
                acc0[r] = fma2(at.x, px0.x, acc0[r]);
                acc0[r] = fma2(at.y, px0.y, acc0[r]);
                acc1[r] = fma2(at.x, px1.x, acc1[r]);
                acc1[r] = fma2(at.y, px1.y, acc1[r]);
            }
        }

        #pragma unroll
        for (int r = 0; r < 7; r++) {
            int i = I0 + 4 * r;
            if (i < NTOT) {
                float* dst;
                if (i < N_AQI) dst = out + ((size_t)b * N_AQI + i) * 64;
                else dst = out + (size_t)BATCH * N_AQI * 64 + ((size_t)b * N_MEO + (i - N_AQI)) * 64;
                dst[F0]     = lo32(acc0[r]) + hi32(acc0[r]);
                dst[F0 + 8] = lo32(acc1[r]) + hi32(acc1[r]);
            }
        }
    }
}

extern "C" void kernel_launch(void* const* d_in, const int* in_sizes, int n_in,
                              void* d_out, int out_size)
{
    const float* aqi_inp      = (const float*)d_in[0];
    const float* meo_inp      = (const float*)d_in[1];
    const float* context_feat = (const float*)d_in[2];
    const float* adj_norm     = (const float*)d_in[3];
    const float* aqi_idE      = (const float*)d_in[4];
    const float* aqi_monthE   = (const float*)d_in[5];
    const float* aqi_weekdayE = (const float*)d_in[6];
    const float* aqi_hourE    = (const float*)d_in[7];
    const float* meo_windE    = (const float*)d_in[8];
    const float* meo_idE      = (const float*)d_in[9];
    const float* meo_monthE   = (const float*)d_in[10];
    const float* meo_weekdayE = (const float*)d_in[11];
    const float* meo_hourE    = (const float*)d_in[12];
    const float* W_xa         = (const float*)d_in[13];
    const float* W_xm         = (const float*)d_in[14];
    const float* W_ua         = (const float*)d_in[15];
    const float* W_um         = (const float*)d_in[16];
    const float* a_aa         = (const float*)d_in[17];
    const float* a_am         = (const float*)d_in[18];
    const float* a_ma         = (const float*)d_in[19];
    const float* a_mm         = (const float*)d_in[20];
    const int*   aqi_ex       = (const int*)d_in[21];
    const int*   meo_ex       = (const int*)d_in[22];
    const int*   adj          = (const int*)d_in[23];
    float* out = (float*)d_out;

    precompute_kernel<<<1, 256>>>(context_feat, adj_norm,
                                  a_aa, a_am, a_ma, a_mm,
                                  W_ua, W_um, W_xa, W_xm, adj);
    hgat_kernel<<<BATCH, 256>>>(aqi_inp, meo_inp,
                                aqi_idE, aqi_monthE, aqi_weekdayE, aqi_hourE,
                                meo_windE, meo_idE, meo_monthE, meo_weekdayE, meo_hourE,
                                aqi_ex, meo_ex, out);
}

// round 6
// speedup vs baseline: 1.0197x; 1.0197x over previous
#include <cuda_runtime.h>
#include <cuda_bf16.h>
#include <cstddef>
#include <cstdint>

#define N_AQI 35
#define N_MEO 18
#define NTOT  53
#define F_OUT 64
#define CTXD  60
#define BATCH 4096
#define NEGV  (-1e12f)
#define LALPHA 0.2f

#define WT_STRIDE  20
#define FULL_STRIDE 28

// ---------------- batch-independent precomputed state ----------------
__device__ float g_bias[NTOT * NTOT];
__device__ unsigned int g_mask[NTOT][2];
__device__ __align__(16) float g_wsrc[2][2][FULL_STRIDE];
__device__ __align__(16) float g_wdst[2][2][FULL_STRIDE];
__device__ __align__(16) float g_WxaT[64 * WT_STRIDE];
__device__ __align__(16) float g_WxmT[64 * WT_STRIDE];

__global__ void precompute_kernel(
    const float* __restrict__ ctx,
    const float* __restrict__ adj_norm,
    const float* __restrict__ a_aa, const float* __restrict__ a_am,
    const float* __restrict__ a_ma, const float* __restrict__ a_mm,
    const float* __restrict__ W_ua, const float* __restrict__ W_um,
    const float* __restrict__ W_xa, const float* __restrict__ W_xm,
    const int*   __restrict__ adj)
{
    __shared__ float s_cs[NTOT][2];
    __shared__ float s_ct[NTOT][2];
    const int tid = threadIdx.x;
    const float* A[2][2] = {{a_aa, a_am}, {a_ma, a_mm}};

    for (int id = tid; id < NTOT * 4; id += blockDim.x) {
        int i = id % NTOT;
        int sel = id / NTOT;
        if (sel < 2) {
            int rb = (i < N_AQI) ? 0 : 1;
            const float* a = A[rb][sel];
            float acc = 0.f;
            for (int c = 0; c < CTXD; c++) acc += ctx[i * CTXD + c] * a[64 + c];
            s_cs[i][sel] = acc;
        } else {
            int rb = sel - 2;
            int cb = (i < N_AQI) ? 0 : 1;
            const float* a = A[rb][cb];
            float acc = 0.f;
            for (int c = 0; c < CTXD; c++) acc += ctx[i * CTXD + c] * a[188 + c];
            s_ct[i][rb] = acc;
        }
    }

    for (int id = tid; id < 2 * 2 * 2 * FULL_STRIDE; id += blockDim.x) {
        int k = id % FULL_STRIDE;
        int r = id / FULL_STRIDE;
        int which = r >> 2;
        int t0 = (r >> 1) & 1;
        int t1 = r & 1;
        const float* W = (t0 == 0) ? W_ua : W_um;
        int K = (t0 == 0) ? 24 : 26;
        float acc = 0.f;
        if (k < K) {
            const float* a = (which == 0) ? A[t0][t1] : A[t1][t0];
            int off = (which == 0) ? 0 : 124;
            for (int f = 0; f < 64; f++) acc += W[k * 64 + f] * a[off + f];
        }
        if (which == 0) g_wsrc[t0][t1][k] = acc;
        else            g_wdst[t0][t1][k] = acc;
    }

    for (int id = tid; id < 64 * WT_STRIDE; id += blockDim.x) {
        int f = id / WT_STRIDE, k = id % WT_STRIDE;
        g_WxaT[id] = (k < 16) ? W_xa[k * 64 + f] : 0.f;
        g_WxmT[id] = (k < 16) ? W_xm[k * 64 + f] : 0.f;
    }

    for (int i = tid; i < NTOT; i += blockDim.x) {
        unsigned int m0 = 0, m1 = 0;
        for (int j = 0; j < 32; j++)   if (adj[i * NTOT + j] > 0) m0 |= (1u << j);
        for (int j = 32; j < NTOT; j++) if (adj[i * NTOT + j] > 0) m1 |= (1u << (j - 32));
        g_mask[i][0] = m0; g_mask[i][1] = m1;
    }
    __syncthreads();

    for (int id = tid; id < NTOT * NTOT; id += blockDim.x) {
        int i = id / NTOT, j = id % NTOT;
        int rb = (i < N_AQI) ? 0 : 1;
        int cb = (j < N_AQI) ? 0 : 1;
        g_bias[id] = s_cs[i][cb] + s_ct[j][rb] + adj_norm[id] * A[rb][cb][248];
    }
}

// ---------------- helpers ----------------
__device__ __forceinline__ unsigned long long fma2(unsigned long long a,
                                                   unsigned long long b,
                                                   unsigned long long c)
{
    unsigned long long d;
    asm("fma.rn.f32x2 %0, %1, %2, %3;" : "=l"(d) : "l"(a), "l"(b), "l"(c));
    return d;
}
__device__ __forceinline__ float lo32(unsigned long long v) { return __uint_as_float((unsigned)v); }
__device__ __forceinline__ float hi32(unsigned long long v) { return __uint_as_float((unsigned)(v >> 32)); }

__device__ __forceinline__ uint32_t smem_u32(const void* p) {
    uint32_t a;
    asm("{ .reg .u64 t; cvta.to.shared.u64 t, %1; cvt.u32.u64 %0, t; }" : "=r"(a) : "l"(p));
    return a;
}
// SW128-style swizzled bf16 store into a tile with 128B rows (1024B-aligned base)
__device__ __forceinline__ void st_bf16_sw(unsigned char* base, uint32_t off, __nv_bfloat16 v) {
    *reinterpret_cast<__nv_bfloat16*>(base + (off ^ ((off >> 3) & 0x70))) = v;
}
__device__ __forceinline__ void bf16_split(float p, __nv_bfloat16& h, __nv_bfloat16& l) {
    h = __float2bfloat16(p);
    l = __float2bfloat16(p - __bfloat162float(h));
}

__device__ __forceinline__ void ldmx4(uint32_t addr, uint32_t& r0, uint32_t& r1,
                                      uint32_t& r2, uint32_t& r3)
{
    asm volatile("ldmatrix.sync.aligned.m8n8.x4.shared.b16 {%0,%1,%2,%3}, [%4];"
                 : "=r"(r0), "=r"(r1), "=r"(r2), "=r"(r3) : "r"(addr));
}
__device__ __forceinline__ void mma16816(float* d, const uint32_t* a, uint32_t b0, uint32_t b1)
{
    asm volatile(
        "mma.sync.aligned.m16n8k16.row.col.f32.bf16.bf16.f32 "
        "{%0,%1,%2,%3}, {%4,%5,%6,%7}, {%8,%9}, {%0,%1,%2,%3};"
        : "+f"(d[0]), "+f"(d[1]), "+f"(d[2]), "+f"(d[3])
        : "r"(a[0]), "r"(a[1]), "r"(a[2]), "r"(a[3]), "r"(b0), "r"(b1));
}

// ---------------- main kernel: one CTA per batch element ----------------
__global__ __launch_bounds__(256, 4) void hgat_kernel(
    const float* __restrict__ aqi_inp, const float* __restrict__ meo_inp,
    const float* __restrict__ aqi_idE, const float* __restrict__ aqi_monthE,
    const float* __restrict__ aqi_weekdayE, const float* __restrict__ aqi_hourE,
    const float* __restrict__ meo_windE, const float* __restrict__ meo_idE,
    const float* __restrict__ meo_monthE, const float* __restrict__ meo_weekdayE,
    const float* __restrict__ meo_hourE,
    const int* __restrict__ aqi_ex, const int* __restrict__ meo_ex,
    float* __restrict__ out)
{
    // A: 128x64 bf16, SW128 rows. Row 2i = attn_hi[i], row 2i+1 = attn_lo[i].
    // B: 128x64 bf16, SW128 rows. Rows 0-63 = pxT_hi[f][node], 64-127 = pxT_lo.
    __shared__ __align__(1024) unsigned char s_A[128 * 128];
    __shared__ __align__(1024) unsigned char s_B[128 * 128];
    __shared__ float s_full[56 * FULL_STRIDE];
    __shared__ float s_S[NTOT * 2];
    __shared__ float s_T[NTOT * 2];

    const int tid = threadIdx.x;
    const int wid = tid >> 5;
    const int lane = tid & 31;
    const int b = blockIdx.x;

    // ---- Phase 0: zero tiles, gather full feature rows ----
    {
        float4 z = make_float4(0.f, 0.f, 0.f, 0.f);
        float4* za = reinterpret_cast<float4*>(s_A);
        float4* zb = reinterpret_cast<float4*>(s_B);
        #pragma unroll
        for (int it = 0; it < 4; it++) { za[tid + it * 256] = z; zb[tid + it * 256] = z; }
    }
    for (int id = tid; id < N_AQI * FULL_STRIDE; id += 256) {
        int i = id / FULL_STRIDE, c = id % FULL_STRIDE;
        float v = 0.f;
        if (c < 16) v = aqi_inp[((size_t)b * N_AQI + i) * 16 + c];
        else if (c < 24) {
            int e = (c - 16) >> 1, comp = (c - 16) & 1;
            int ix = aqi_ex[((size_t)b * N_AQI + i) * 4 + e];
            const float* tab = (e == 0) ? aqi_idE : (e == 1) ? aqi_monthE
                             : (e == 2) ? aqi_weekdayE : aqi_hourE;
            v = tab[ix * 2 + comp];
        }
        s_full[i * FULL_STRIDE + c] = v;
    }
    for (int id = tid; id < N_MEO * FULL_STRIDE; id += 256) {
        int i = id / FULL_STRIDE, c = id % FULL_STRIDE;
        float v = 0.f;
        if (c < 16) v = meo_inp[((size_t)b * N_MEO + i) * 16 + c];
        else if (c < 26) {
            int e = (c - 16) >> 1, comp = (c - 16) & 1;
            int ix = meo_ex[((size_t)b * N_MEO + i) * 5 + e];
            const float* tab = (e == 0) ? meo_windE : (e == 1) ? meo_idE
                             : (e == 2) ? meo_monthE : (e == 3) ? meo_weekdayE : meo_hourE;
            v = tab[ix * 2 + comp];
        }
        s_full[(N_AQI + i) * FULL_STRIDE + c] = v;
    }
    __syncthreads();

    // ---- Phase 1: projxT = (full @ W_x)^T -> bf16 hi/lo into B tile ----
    {
        const int f = tid & 63, rg = tid >> 6;
        const float* wta = g_WxaT + f * WT_STRIDE;
        const float* wtm = g_WxmT + f * WT_STRIDE;

        unsigned long long accA[9];
        #pragma unroll
        for (int r = 0; r < 9; r++) accA[r] = 0ull;
        #pragma unroll
        for (int kg = 0; kg < 4; kg++) {
            ulonglong2 wv = *reinterpret_cast<const ulonglong2*>(wta + 4 * kg);
            #pragma unroll
            for (int r = 0; r < 9; r++) {
                int n = rg + 4 * r;
                ulonglong2 xv = *reinterpret_cast<const ulonglong2*>(&s_full[n * FULL_STRIDE + 4 * kg]);
                accA[r] = fma2(wv.x, xv.x, accA[r]);
                accA[r] = fma2(wv.y, xv.y, accA[r]);
            }
        }
        #pragma unroll
        for (int r = 0; r < 9; r++) {
            int n = rg + 4 * r;
            if (n < N_AQI) {
                float p = lo32(accA[r]) + hi32(accA[r]);
                __nv_bfloat16 h, l;
                bf16_split(p, h, l);
                st_bf16_sw(s_B, (uint32_t)(f * 128 + n * 2), h);
                st_bf16_sw(s_B, (uint32_t)((64 + f) * 128 + n * 2), l);
            }
        }

        unsigned long long accM[5];
        #pragma unroll
        for (int r = 0; r < 5; r++) accM[r] = 0ull;
        #pragma unroll
        for (int kg = 0; kg < 4; kg++) {
            ulonglong2 wv = *reinterpret_cast<const ulonglong2*>(wtm + 4 * kg);
            #pragma unroll
            for (int r = 0; r < 5; r++) {
                int n = rg + 4 * r;
                ulonglong2 xv = *reinterpret_cast<const ulonglong2*>(&s_full[(N_AQI + n) * FULL_STRIDE + 4 * kg]);
                accM[r] = fma2(wv.x, xv.x, accM[r]);
                accM[r] = fma2(wv.y, xv.y, accM[r]);
            }
        }
        #pragma unroll
        for (int r = 0; r < 5; r++) {
            int n = rg + 4 * r;
            if (n < N_MEO) {
                float p = lo32(accM[r]) + hi32(accM[r]);
                __nv_bfloat16 h, l;
                bf16_split(p, h, l);
                st_bf16_sw(s_B, (uint32_t)(f * 128 + (N_AQI + n) * 2), h);
                st_bf16_sw(s_B, (uint32_t)((64 + f) * 128 + (N_AQI + n) * 2), l);
            }
        }
    }

    // ---- Phase 2: S[i][cb], T[j][rb] via folded vectors ----
    if (tid < NTOT * 4) {
        int i = tid % NTOT;
        int sel = tid / NTOT;
        int rt = (i < N_AQI) ? 0 : 1;
        const float4* xr = reinterpret_cast<const float4*>(&s_full[i * FULL_STRIDE]);
        const float4* wv = reinterpret_cast<const float4*>(
            (sel < 2) ? g_wsrc[rt][sel] : g_wdst[rt][sel - 2]);
        float acc = 0.f;
        #pragma unroll
        for (int m = 0; m < 7; m++) {
            float4 x = xr[m], w = wv[m];
            acc += x.x * w.x + x.y * w.y + x.z * w.z + x.w * w.w;
        }
        if (sel < 2) s_S[i * 2 + sel] = acc;
        else         s_T[i * 2 + (sel - 2)] = acc;
    }
    __syncthreads();

    // ---- Phase 3: masked softmax -> bf16 hi/lo into A tile rows 2i / 2i+1 ----
    {
        const int w = wid;
        const int j1 = lane, j2 = lane + 32;
        const int cb1 = (j1 < N_AQI) ? 0 : 1;
        const int cb2 = (j2 < N_AQI) ? 0 : 1;
        const float t1_0 = s_T[j1 * 2 + 0], t1_1 = s_T[j1 * 2 + 1];
        const bool v2 = (j2 < NTOT);
        const float t2_0 = v2 ? s_T[j2 * 2 + 0] : 0.f;
        const float t2_1 = v2 ? s_T[j2 * 2 + 1] : 0.f;

        for (int i = w; i < NTOT; i += 8) {
            const int rb = (i < N_AQI) ? 0 : 1;
            const unsigned int m0 = g_mask[i][0], m1 = g_mask[i][1];
            float e1, e2;
            {
                float v = s_S[i * 2 + cb1] + (rb ? t1_1 : t1_0) + g_bias[i * NTOT + j1];
                v = (v >= 0.f) ? v : LALPHA * v;
                e1 = ((m0 >> j1) & 1u) ? v : NEGV;
            }
            if (v2) {
                float v = s_S[i * 2 + cb2] + (rb ? t2_1 : t2_0) + g_bias[i * NTOT + j2];
                v = (v >= 0.f) ? v : LALPHA * v;
                e2 = ((m1 >> (j2 - 32)) & 1u) ? v : NEGV;
            } else {
                e2 = -3.4e38f;
            }
            float mx = fmaxf(e1, e2);
            #pragma unroll
            for (int o = 16; o > 0; o >>= 1) mx = fmaxf(mx, __shfl_xor_sync(0xffffffffu, mx, o));
            float p1 = __expf(e1 - mx);
            float p2 = v2 ? __expf(e2 - mx) : 0.f;
            float sum = p1 + p2;
            #pragma unroll
            for (int o = 16; o > 0; o >>= 1) sum += __shfl_xor_sync(0xffffffffu, sum, o);
            float inv = 1.f / sum;
            {
                __nv_bfloat16 h, l;
                bf16_split(p1 * inv, h, l);
                st_bf16_sw(s_A, (uint32_t)((2 * i) * 128 + j1 * 2), h);
                st_bf16_sw(s_A, (uint32_t)((2 * i + 1) * 128 + j1 * 2), l);
            }
            if (v2) {
                __nv_bfloat16 h, l;
                bf16_split(p2 * inv, h, l);
                st_bf16_sw(s_A, (uint32_t)((2 * i) * 128 + j2 * 2), h);
                st_bf16_sw(s_A, (uint32_t)((2 * i + 1) * 128 + j2 * 2), l);
            }
        }
    }
    __syncthreads();

    // ---- Phase 4: D = A @ B^T via mma.sync m16n8k16 bf16 ----
    // warp = (mg: 32 A-rows) x (ng: 32 feats). 64 MMAs/warp, 24 ldmatrix.x4.
    {
        const int mg = wid >> 1, ng = wid & 1;
        const int lm = lane >> 3, lr = lane & 7;
        const uint32_t aBase = smem_u32(s_A);
        const uint32_t bBase = smem_u32(s_B);
        const uint32_t swx = (uint32_t)(lr << 4);          // row-swizzle XOR (row&7 == lr)
        const uint32_t aCol = (uint32_t)((lm >> 1) << 4);  // A matrix col offset
        const uint32_t bCol = (uint32_t)((lm & 1) << 4);   // B matrix col offset

        // A row base per m-tile; B row base per (half, n-tile-pair)
        uint32_t aRB[2], bRB[2][2];
        #pragma unroll
        for (int mt = 0; mt < 2; mt++) {
            int row = mg * 32 + mt * 16 + (lm & 1) * 8 + lr;
            aRB[mt] = aBase + (uint32_t)(row * 128);
        }
        #pragma unroll
        for (int h = 0; h < 2; h++)
            #pragma unroll
            for (int ntp = 0; ntp < 2; ntp++) {
                int row = h * 64 + ng * 32 + ntp * 16 + (lm >> 1) * 8 + lr;
                bRB[h][ntp] = bBase + (uint32_t)(row * 128);
            }

        float d[2][4][4];
        #pragma unroll
        for (int mt = 0; mt < 2; mt++)
            #pragma unroll
            for (int nt = 0; nt < 4; nt++)
                #pragma unroll
                for (int q = 0; q < 4; q++) d[mt][nt][q] = 0.f;

        #pragma unroll
        for (int k = 0; k < 4; k++) {
            uint32_t a[2][4];
            #pragma unroll
            for (int mt = 0; mt < 2; mt++)
                ldmx4(aRB[mt] + (((uint32_t)(k << 5) + aCol) ^ swx),
                      a[mt][0], a[mt][1], a[mt][2], a[mt][3]);
            #pragma unroll
            for (int h = 0; h < 2; h++) {
                #pragma unroll
                for (int ntp = 0; ntp < 2; ntp++) {
                    uint32_t b0, b1, b2, b3;
                    ldmx4(bRB[h][ntp] + (((uint32_t)(k << 5) + bCol) ^ swx), b0, b1, b2, b3);
                    #pragma unroll
                    for (int mt = 0; mt < 2; mt++) {
                        mma16816(d[mt][ntp * 2 + 0], a[mt], b0, b1);
                        mma16816(d[mt][ntp * 2 + 1], a[mt], b2, b3);
                    }
                }
            }
        }

        // Epilogue: sum row pairs (2i hi + 2i+1 lo) via shfl_xor(4), store float2.
        const int rowg = lane >> 2;
        const bool keep = ((rowg & 1) == 0);
        const int colb = ng * 32 + (lane & 3) * 2;
        #pragma unroll
        for (int mt = 0; mt < 2; mt++) {
            #pragma unroll
            for (int nt = 0; nt < 4; nt++) {
                float s0 = d[mt][nt][0] + __shfl_xor_sync(0xffffffffu, d[mt][nt][0], 4);
                float s1 = d[mt][nt][1] + __shfl_xor_sync(0xffffffffu, d[mt][nt][1], 4);
                float s2 = d[mt][nt][2] + __shfl_xor_sync(0xffffffffu, d[mt][nt][2], 4);
                float s3 = d[mt][nt][3] + __shfl_xor_sync(0xffffffffu, d[mt][nt][3], 4);
                if (keep) {
                    int n01 = mg * 16 + mt * 8 + (rowg >> 1);
                    int n23 = n01 + 4;
                    int col = colb + nt * 8;
                    if (n01 < NTOT) {
                        float* dst = (n01 < N_AQI)
                            ? out + ((size_t)b * N_AQI + n01) * 64
                            : out + (size_t)BATCH * N_AQI * 64 + ((size_t)b * N_MEO + (n01 - N_AQI)) * 64;
                        *reinterpret_cast<float2*>(dst + col) = make_float2(s0, s1);
                    }
                    if (n23 < NTOT) {
                        float* dst = (n23 < N_AQI)
                            ? out + ((size_t)b * N_AQI + n23) * 64
                            : out + (size_t)BATCH * N_AQI * 64 + ((size_t)b * N_MEO + (n23 - N_AQI)) * 64;
                        *reinterpret_cast<float2*>(dst + col) = make_float2(s2, s3);
                    }
                }
            }
        }
    }
}

extern "C" void kernel_launch(void* const* d_in, const int* in_sizes, int n_in,
                              void* d_out, int out_size)
{
    const float* aqi_inp      = (const float*)d_in[0];
    const float* meo_inp      = (const float*)d_in[1];
    const float* context_feat = (const float*)d_in[2];
    const float* adj_norm     = (const float*)d_in[3];
    const float* aqi_idE      = (const float*)d_in[4];
    const float* aqi_monthE   = (const float*)d_in[5];
    const float* aqi_weekdayE = (const float*)d_in[6];
    const float* aqi_hourE    = (const float*)d_in[7];
    const float* meo_windE    = (const float*)d_in[8];
    const float* meo_idE      = (const float*)d_in[9];
    const float* meo_monthE   = (const float*)d_in[10];
    const float* meo_weekdayE = (const float*)d_in[11];
    const float* meo_hourE    = (const float*)d_in[12];
    const float* W_xa         = (const float*)d_in[13];
    const float* W_xm         = (const float*)d_in[14];
    const float* W_ua         = (const float*)d_in[15];
    const float* W_um         = (const float*)d_in[16];
    const float* a_aa         = (const float*)d_in[17];
    const float* a_am         = (const float*)d_in[18];
    const float* a_ma         = (const float*)d_in[19];
    const float* a_mm         = (const float*)d_in[20];
    const int*   aqi_ex       = (const int*)d_in[21];
    const int*   meo_ex       = (const int*)d_in[22];
    const int*   adj          = (const int*)d_in[23];
    float* out = (float*)d_out;

    precompute_kernel<<<1, 256>>>(context_feat, adj_norm,
                                  a_aa, a_am, a_ma, a_mm,
                                  W_ua, W_um, W_xa, W_xm, adj);
    hgat_kernel<<<BATCH, 256>>>(aqi_inp, meo_inp,
                                aqi_idE, aqi_monthE, aqi_weekdayE, aqi_hourE,
                                meo_windE, meo_idE, meo_monthE, meo_weekdayE, meo_hourE,
                                aqi_ex, meo_ex, out);
}

// round 8
// speedup vs baseline: 1.1257x; 1.1039x over previous
#include <cuda_runtime.h>
#include <cuda_bf16.h>
#include <cstddef>
#include <cstdint>

#define N_AQI 35
#define N_MEO 18
#define NTOT  53
#define F_OUT 64
#define CTXD  60
#define BATCH 4096
#define NEGV  (-1e12f)
#define LALPHA 0.2f

#define WT_STRIDE  20
#define FULL_STRIDE 28

// K-column permutation: col c -> node j. MEO first (even-aligned pairs everywhere).
//   c in [0,18)  -> j = 35 + c   (MEO)
//   c in [18,53) -> j = c - 18   (AQI)

// ---------------- batch-independent precomputed state ----------------
__device__ __align__(16) float g_biasP[NTOT * 56];       // permuted cols, padded to 56
__device__ __align__(16) unsigned long long g_maskP[NTOT];
__device__ __align__(16) float g_wsrc[2][2][FULL_STRIDE];
__device__ __align__(16) float g_wdst[2][2][FULL_STRIDE];
__device__ __align__(16) float g_WxaT[64 * WT_STRIDE];
__device__ __align__(16) float g_WxmT[64 * WT_STRIDE];

__global__ void precompute_kernel(
    const float* __restrict__ ctx,
    const float* __restrict__ adj_norm,
    const float* __restrict__ a_aa, const float* __restrict__ a_am,
    const float* __restrict__ a_ma, const float* __restrict__ a_mm,
    const float* __restrict__ W_ua, const float* __restrict__ W_um,
    const float* __restrict__ W_xa, const float* __restrict__ W_xm,
    const int*   __restrict__ adj)
{
    __shared__ float s_cs[NTOT][2];
    __shared__ float s_ct[NTOT][2];
    const int tid = threadIdx.x;
    const float* A[2][2] = {{a_aa, a_am}, {a_ma, a_mm}};

    for (int id = tid; id < NTOT * 4; id += blockDim.x) {
        int i = id % NTOT;
        int sel = id / NTOT;
        if (sel < 2) {
            int rb = (i < N_AQI) ? 0 : 1;
            const float* a = A[rb][sel];
            float acc = 0.f;
            for (int c = 0; c < CTXD; c++) acc += ctx[i * CTXD + c] * a[64 + c];
            s_cs[i][sel] = acc;
        } else {
            int rb = sel - 2;
            int cb = (i < N_AQI) ? 0 : 1;
            const float* a = A[rb][cb];
            float acc = 0.f;
            for (int c = 0; c < CTXD; c++) acc += ctx[i * CTXD + c] * a[188 + c];
            s_ct[i][rb] = acc;
        }
    }

    for (int id = tid; id < 2 * 2 * 2 * FULL_STRIDE; id += blockDim.x) {
        int k = id % FULL_STRIDE;
        int r = id / FULL_STRIDE;
        int which = r >> 2;
        int t0 = (r >> 1) & 1;
        int t1 = r & 1;
        const float* W = (t0 == 0) ? W_ua : W_um;
        int K = (t0 == 0) ? 24 : 26;
        float acc = 0.f;
        if (k < K) {
            const float* a = (which == 0) ? A[t0][t1] : A[t1][t0];
            int off = (which == 0) ? 0 : 124;
            for (int f = 0; f < 64; f++) acc += W[k * 64 + f] * a[off + f];
        }
        if (which == 0) g_wsrc[t0][t1][k] = acc;
        else            g_wdst[t0][t1][k] = acc;
    }

    for (int id = tid; id < 64 * WT_STRIDE; id += blockDim.x) {
        int f = id / WT_STRIDE, k = id % WT_STRIDE;
        g_WxaT[id] = (k < 16) ? W_xa[k * 64 + f] : 0.f;
        g_WxmT[id] = (k < 16) ? W_xm[k * 64 + f] : 0.f;
    }

    for (int i = tid; i < NTOT; i += blockDim.x) {
        unsigned long long m = 0ull;
        for (int c = 0; c < NTOT; c++) {
            int j = (c < 18) ? 35 + c : c - 18;
            if (adj[i * NTOT + j] > 0) m |= (1ull << c);
        }
        g_maskP[i] = m;
    }
    __syncthreads();

    for (int id = tid; id < NTOT * 56; id += blockDim.x) {
        int i = id / 56, c = id % 56;
        float v = 0.f;
        if (c < NTOT) {
            int j = (c < 18) ? 35 + c : c - 18;
            int rb = (i < N_AQI) ? 0 : 1;
            int cb = (j < N_AQI) ? 0 : 1;
            v = s_cs[i][cb] + s_ct[j][rb] + adj_norm[i * NTOT + j] * A[rb][cb][248];
        }
        g_biasP[id] = v;
    }
}

// ---------------- helpers ----------------
__device__ __forceinline__ unsigned long long fma2(unsigned long long a,
                                                   unsigned long long b,
                                                   unsigned long long c)
{
    unsigned long long d;
    asm("fma.rn.f32x2 %0, %1, %2, %3;" : "=l"(d) : "l"(a), "l"(b), "l"(c));
    return d;
}
__device__ __forceinline__ float lo32(unsigned long long v) { return __uint_as_float((unsigned)v); }
__device__ __forceinline__ float hi32(unsigned long long v) { return __uint_as_float((unsigned)(v >> 32)); }

__device__ __forceinline__ uint32_t smem_u32(const void* p) {
    uint32_t a;
    asm("{ .reg .u64 t; cvta.to.shared.u64 t, %1; cvt.u32.u64 %0, t; }" : "=r"(a) : "l"(p));
    return a;
}
__device__ __forceinline__ void bf16_split(float p, __nv_bfloat16& h, __nv_bfloat16& l) {
    h = __float2bfloat16(p);
    l = __float2bfloat16(p - __bfloat162float(h));
}
__device__ __forceinline__ uint32_t pack2(__nv_bfloat16 a, __nv_bfloat16 b) {
    __nv_bfloat162 v = __halves2bfloat162(a, b);   // a -> low halfword
    return *reinterpret_cast<uint32_t*>(&v);
}
__device__ __forceinline__ void ldmx4(uint32_t addr, uint32_t& r0, uint32_t& r1,
                                      uint32_t& r2, uint32_t& r3)
{
    asm volatile("ldmatrix.sync.aligned.m8n8.x4.shared.b16 {%0,%1,%2,%3}, [%4];"
                 : "=r"(r0), "=r"(r1), "=r"(r2), "=r"(r3) : "r"(addr));
}
__device__ __forceinline__ void mma16816(float* d, const uint32_t* a, uint32_t b0, uint32_t b1)
{
    asm volatile(
        "mma.sync.aligned.m16n8k16.row.col.f32.bf16.bf16.f32 "
        "{%0,%1,%2,%3}, {%4,%5,%6,%7}, {%8,%9}, {%0,%1,%2,%3};"
        : "+f"(d[0]), "+f"(d[1]), "+f"(d[2]), "+f"(d[3])
        : "r"(a[0]), "r"(a[1]), "r"(a[2]), "r"(a[3]), "r"(b0), "r"(b1));
}

// ---------------- main kernel: one CTA per batch element ----------------
__global__ __launch_bounds__(256, 4) void hgat_kernel(
    const float* __restrict__ aqi_inp, const float* __restrict__ meo_inp,
    const float* __restrict__ aqi_idE, const float* __restrict__ aqi_monthE,
    const float* __restrict__ aqi_weekdayE, const float* __restrict__ aqi_hourE,
    const float* __restrict__ meo_windE, const float* __restrict__ meo_idE,
    const float* __restrict__ meo_monthE, const float* __restrict__ meo_weekdayE,
    const float* __restrict__ meo_hourE,
    const int* __restrict__ aqi_ex, const int* __restrict__ meo_ex,
    float* __restrict__ out)
{
    // A: 128x64 bf16 SW128. Row 2i = attn_hi[i] (permuted cols), 2i+1 = attn_lo[i].
    // B: 128x64 bf16 SW128. Row f = pxT_hi[f] (permuted cols), 64+f = pxT_lo[f].
    __shared__ __align__(1024) unsigned char s_A[128 * 128];
    __shared__ __align__(1024) unsigned char s_B[128 * 128];
    __shared__ __align__(16) float s_full[56 * FULL_STRIDE];
    __shared__ __align__(16) float s_S[NTOT * 2];
    __shared__ __align__(16) float s_T[54 * 2];   // permuted-col index, col 53 zeroed

    const int tid = threadIdx.x;
    const int wid = tid >> 5;
    const int lane = tid & 31;
    const int b = blockIdx.x;

    // ---- Phase 0: K-pad zeroing, feature copy, embedding gather ----
    {
        const float4 z4 = make_float4(0.f, 0.f, 0.f, 0.f);
        // zero logical bytes [96,128) of every tile row (swizzle-mapped 16B chunks)
        {
            int row = tid & 127;
            unsigned char* base = (tid < 128) ? s_A : s_B;
            uint32_t sw = (uint32_t)((row & 7) << 4);
            *reinterpret_cast<float4*>(base + row * 128 + (96u ^ sw)) = z4;
            *reinterpret_cast<float4*>(base + row * 128 + (112u ^ sw)) = z4;
        }
        // input features: 53 rows x 4 float4
        if (tid < NTOT * 4) {
            int row = tid >> 2, q = tid & 3;
            float4 v = (row < N_AQI)
                ? *reinterpret_cast<const float4*>(&aqi_inp[((size_t)b * N_AQI + row) * 16 + 4 * q])
                : *reinterpret_cast<const float4*>(&meo_inp[((size_t)b * N_MEO + (row - N_AQI)) * 16 + 4 * q]);
            *reinterpret_cast<float4*>(&s_full[row * FULL_STRIDE + 4 * q]) = v;
        }
        // AQI embeddings: 35 rows x 4 slots (float2 each)
        for (int id = tid; id < N_AQI * 4; id += 256) {
            int row = id >> 2, e = id & 3;
            int ix = aqi_ex[((size_t)b * N_AQI + row) * 4 + e];
            const float* tab = (e == 0) ? aqi_idE : (e == 1) ? aqi_monthE
                             : (e == 2) ? aqi_weekdayE : aqi_hourE;
            *reinterpret_cast<float2*>(&s_full[row * FULL_STRIDE + 16 + 2 * e]) =
                *reinterpret_cast<const float2*>(&tab[ix * 2]);
        }
        // MEO embeddings: 18 rows x 5 slots
        for (int id = tid; id < N_MEO * 5; id += 256) {
            int row = id / 5, e = id - row * 5;
            int ix = meo_ex[((size_t)b * N_MEO + row) * 5 + e];
            const float* tab = (e == 0) ? meo_windE : (e == 1) ? meo_idE
                             : (e == 2) ? meo_monthE : (e == 3) ? meo_weekdayE : meo_hourE;
            *reinterpret_cast<float2*>(&s_full[(N_AQI + row) * FULL_STRIDE + 16 + 2 * e]) =
                *reinterpret_cast<const float2*>(&tab[ix * 2]);
        }
        // s_full pads: AQI cols 24-27, MEO cols 26-27; s_T col 53
        if (tid < N_AQI) {
            *reinterpret_cast<float4*>(&s_full[tid * FULL_STRIDE + 24]) = z4;
        } else if (tid < NTOT) {
            s_full[tid * FULL_STRIDE + 26] = 0.f;
            s_full[tid * FULL_STRIDE + 27] = 0.f;
        } else if (tid < NTOT + 2) {
            s_T[53 * 2 + (tid - NTOT)] = 0.f;
        }
    }
    __syncthreads();

    // ---- Phase 1: projxT -> bf16 hi/lo pairs into B tile (permuted cols) ----
    {
        const int f = tid >> 2, rg = tid & 3;
        const uint32_t sw = (uint32_t)((f & 7) << 4);
        unsigned char* rowHi = s_B + f * 128;
        unsigned char* rowLo = s_B + (64 + f) * 128;

        // MEO pass: pairs at c0 = 2rg + 8r (c0 < 18), node j0 = 35 + c0
        {
            const float* wt = g_WxmT + f * WT_STRIDE;
            unsigned long long acc[3][2];
            #pragma unroll
            for (int r = 0; r < 3; r++) { acc[r][0] = 0ull; acc[r][1] = 0ull; }
            #pragma unroll
            for (int kg = 0; kg < 4; kg++) {
                ulonglong2 wv = *reinterpret_cast<const ulonglong2*>(wt + 4 * kg);
                #pragma unroll
                for (int r = 0; r < 3; r++) {
                    int c0 = 2 * rg + 8 * r;
                    if (c0 < 18) {
                        const float* x0 = &s_full[(N_AQI + c0) * FULL_STRIDE + 4 * kg];
                        ulonglong2 a0 = *reinterpret_cast<const ulonglong2*>(x0);
                        ulonglong2 a1 = *reinterpret_cast<const ulonglong2*>(x0 + FULL_STRIDE);
                        acc[r][0] = fma2(wv.x, a0.x, acc[r][0]);
                        acc[r][0] = fma2(wv.y, a0.y, acc[r][0]);
                        acc[r][1] = fma2(wv.x, a1.x, acc[r][1]);
                        acc[r][1] = fma2(wv.y, a1.y, acc[r][1]);
                    }
                }
            }
            #pragma unroll
            for (int r = 0; r < 3; r++) {
                int c0 = 2 * rg + 8 * r;
                if (c0 < 18) {
                    float p0 = lo32(acc[r][0]) + hi32(acc[r][0]);
                    float p1 = lo32(acc[r][1]) + hi32(acc[r][1]);
                    __nv_bfloat16 h0, l0, h1, l1;
                    bf16_split(p0, h0, l0);
                    bf16_split(p1, h1, l1);
                    uint32_t off = ((uint32_t)(2 * c0)) ^ sw;
                    *reinterpret_cast<uint32_t*>(rowHi + off) = pack2(h0, h1);
                    *reinterpret_cast<uint32_t*>(rowLo + off) = pack2(l0, l1);
                }
            }
        }
        // AQI pass: pairs at c0 = 18 + 2rg + 8r (c0 <= 52), node j0 = c0 - 18
        {
            const float* wt = g_WxaT + f * WT_STRIDE;
            unsigned long long acc[5][2];
            #pragma unroll
            for (int r = 0; r < 5; r++) { acc[r][0] = 0ull; acc[r][1] = 0ull; }
            #pragma unroll
            for (int kg = 0; kg < 4; kg++) {
                ulonglong2 wv = *reinterpret_cast<const ulonglong2*>(wt + 4 * kg);
                #pragma unroll
                for (int r = 0; r < 5; r++) {
                    int c0 = 18 + 2 * rg + 8 * r;
                    if (c0 <= 52) {
                        const float* x0 = &s_full[(c0 - 18) * FULL_STRIDE + 4 * kg];
                        ulonglong2 a0 = *reinterpret_cast<const ulonglong2*>(x0);
                        ulonglong2 a1 = *reinterpret_cast<const ulonglong2*>(x0 + FULL_STRIDE);
                        acc[r][0] = fma2(wv.x, a0.x, acc[r][0]);
                        acc[r][0] = fma2(wv.y, a0.y, acc[r][0]);
                        acc[r][1] = fma2(wv.x, a1.x, acc[r][1]);
                        acc[r][1] = fma2(wv.y, a1.y, acc[r][1]);
                    }
                }
            }
            #pragma unroll
            for (int r = 0; r < 5; r++) {
                int c0 = 18 + 2 * rg + 8 * r;
                if (c0 <= 52) {
                    float p0 = lo32(acc[r][0]) + hi32(acc[r][0]);
                    float p1 = (c0 == 52) ? 0.f : lo32(acc[r][1]) + hi32(acc[r][1]);
                    __nv_bfloat16 h0, l0, h1, l1;
                    bf16_split(p0, h0, l0);
                    bf16_split(p1, h1, l1);
                    uint32_t off = ((uint32_t)(2 * c0)) ^ sw;
                    *reinterpret_cast<uint32_t*>(rowHi + off) = pack2(h0, h1);
                    *reinterpret_cast<uint32_t*>(rowLo + off) = pack2(l0, l1);
                }
            }
        }
    }

    // ---- Phase 2: S[i][cb]; T -> permuted-col layout ----
    if (tid < NTOT * 4) {
        int i = tid % NTOT;
        int sel = tid / NTOT;
        int rt = (i < N_AQI) ? 0 : 1;
        const float4* xr = reinterpret_cast<const float4*>(&s_full[i * FULL_STRIDE]);
        const float4* wv = reinterpret_cast<const float4*>(
            (sel < 2) ? g_wsrc[rt][sel] : g_wdst[rt][sel - 2]);
        float acc = 0.f;
        #pragma unroll
        for (int m = 0; m < 7; m++) {
            float4 x = xr[m], w = wv[m];
            acc += x.x * w.x + x.y * w.y + x.z * w.z + x.w * w.w;
        }
        if (sel < 2) s_S[i * 2 + sel] = acc;
        else {
            int c = (i < N_AQI) ? i + 18 : i - N_AQI;
            s_T[c * 2 + (sel - 2)] = acc;
        }
    }
    __syncthreads();

    // ---- Phase 3: masked softmax -> packed bf16x2 hi/lo into A tile ----
    {
        const bool act = (lane < 27);
        const int c0 = 2 * lane, c1 = c0 + 1;
        float4 tv = act ? *reinterpret_cast<const float4*>(&s_T[c0 * 2])
                        : make_float4(0.f, 0.f, 0.f, 0.f);
        const bool meo0 = (c0 < 18), meo1 = (c1 < 18);
        const uint32_t colOff = (uint32_t)(4 * lane);

        for (int i = wid; i < NTOT; i += 8) {
            const int rb = (i < N_AQI) ? 0 : 1;
            float e0 = -3.4e38f, e1 = -3.4e38f;
            if (act) {
                unsigned long long M = g_maskP[i];
                float2 sv = *reinterpret_cast<const float2*>(&s_S[i * 2]);
                float2 bp = *reinterpret_cast<const float2*>(&g_biasP[i * 56 + c0]);
                float s0 = meo0 ? sv.y : sv.x;
                float s1 = meo1 ? sv.y : sv.x;
                float t0 = rb ? tv.y : tv.x;
                float t1 = rb ? tv.w : tv.z;
                float v0 = s0 + t0 + bp.x; v0 = (v0 >= 0.f) ? v0 : LALPHA * v0;
                float v1 = s1 + t1 + bp.y; v1 = (v1 >= 0.f) ? v1 : LALPHA * v1;
                e0 = ((M >> c0) & 1ull) ? v0 : NEGV;
                e1 = ((M >> c1) & 1ull) ? v1 : NEGV;
                if (c1 >= NTOT) e1 = -3.4e38f;     // pad col excluded from softmax
            }
            float mx = fmaxf(e0, e1);
            #pragma unroll
            for (int o = 16; o > 0; o >>= 1) mx = fmaxf(mx, __shfl_xor_sync(0xffffffffu, mx, o));
            float p0 = act ? __expf(e0 - mx) : 0.f;
            float p1 = (act && c1 < NTOT) ? __expf(e1 - mx) : 0.f;
            float sum = p0 + p1;
            #pragma unroll
            for (int o = 16; o > 0; o >>= 1) sum += __shfl_xor_sync(0xffffffffu, sum, o);
            float inv = 1.f / sum;
            if (act) {
                p0 *= inv; p1 *= inv;
                __nv_bfloat16 h0, l0, h1, l1;
                bf16_split(p0, h0, l0);
                bf16_split(p1, h1, l1);
                uint32_t rH = (uint32_t)(2 * i);
                uint32_t rL = rH + 1;
                uint32_t offH = rH * 128 + (colOff ^ ((rH & 7) << 4));
                uint32_t offL = rL * 128 + (colOff ^ ((rL & 7) << 4));
                *reinterpret_cast<uint32_t*>(s_A + offH) = pack2(h0, h1);
                *reinterpret_cast<uint32_t*>(s_A + offL) = pack2(l0, l1);
            }
        }
    }
    __syncthreads();

    // ---- Phase 4: D = A @ B^T via mma.sync m16n8k16 bf16 ----
    {
        const int mg = wid >> 1, ng = wid & 1;
        const int lm = lane >> 3, lr = lane & 7;
        const uint32_t aBase = smem_u32(s_A);
        const uint32_t bBase = smem_u32(s_B);
        const uint32_t swx = (uint32_t)(lr << 4);
        const uint32_t aCol = (uint32_t)((lm >> 1) << 4);
        const uint32_t bCol = (uint32_t)((lm & 1) << 4);

        uint32_t aRB[2], bRB[2][2];
        #pragma unroll
        for (int mt = 0; mt < 2; mt++) {
            int row = mg * 32 + mt * 16 + (lm & 1) * 8 + lr;
            aRB[mt] = aBase + (uint32_t)(row * 128);
        }
        #pragma unroll
        for (int h = 0; h < 2; h++)
            #pragma unroll
            for (int ntp = 0; ntp < 2; ntp++) {
                int row = h * 64 + ng * 32 + ntp * 16 + (lm >> 1) * 8 + lr;
                bRB[h][ntp] = bBase + (uint32_t)(row * 128);
            }

        float d[2][4][4];
        #pragma unroll
        for (int mt = 0; mt < 2; mt++)
            #pragma unroll
            for (int nt = 0; nt < 4; nt++)
                #pragma unroll
                for (int q = 0; q < 4; q++) d[mt][nt][q] = 0.f;

        #pragma unroll
        for (int k = 0; k < 4; k++) {
            uint32_t a[2][4];
            #pragma unroll
            for (int mt = 0; mt < 2; mt++)
                ldmx4(aRB[mt] + (((uint32_t)(k << 5) + aCol) ^ swx),
                      a[mt][0], a[mt][1], a[mt][2], a[mt][3]);
            #pragma unroll
            for (int h = 0; h < 2; h++) {
                #pragma unroll
                for (int ntp = 0; ntp < 2; ntp++) {
                    uint32_t b0, b1, b2, b3;
                    ldmx4(bRB[h][ntp] + (((uint32_t)(k << 5) + bCol) ^ swx), b0, b1, b2, b3);
                    #pragma unroll
                    for (int mt = 0; mt < 2; mt++) {
                        mma16816(d[mt][ntp * 2 + 0], a[mt], b0, b1);
                        mma16816(d[mt][ntp * 2 + 1], a[mt], b2, b3);
                    }
                }
            }
        }

        const int rowg = lane >> 2;
        const bool keep = ((rowg & 1) == 0);
        const int colb = ng * 32 + (lane & 3) * 2;
        #pragma unroll
        for (int mt = 0; mt < 2; mt++) {
            #pragma unroll
            for (int nt = 0; nt < 4; nt++) {
                float s0 = d[mt][nt][0] + __shfl_xor_sync(0xffffffffu, d[mt][nt][0], 4);
                float s1 = d[mt][nt][1] + __shfl_xor_sync(0xffffffffu, d[mt][nt][1], 4);
                float s2 = d[mt][nt][2] + __shfl_xor_sync(0xffffffffu, d[mt][nt][2], 4);
                float s3 = d[mt][nt][3] + __shfl_xor_sync(0xffffffffu, d[mt][nt][3], 4);
                if (keep) {
                    int n01 = mg * 16 + mt * 8 + (rowg >> 1);
                    int n23 = n01 + 4;
                    int col = colb + nt * 8;
                    if (n01 < NTOT) {
                        float* dst = (n01 < N_AQI)
                            ? out + ((size_t)b * N_AQI + n01) * 64
                            : out + (size_t)BATCH * N_AQI * 64 + ((size_t)b * N_MEO + (n01 - N_AQI)) * 64;
                        *reinterpret_cast<float2*>(dst + col) = make_float2(s0, s1);
                    }
                    if (n23 < NTOT) {
                        float* dst = (n23 < N_AQI)
                            ? out + ((size_t)b * N_AQI + n23) * 64
                            : out + (size_t)BATCH * N_AQI * 64 + ((size_t)b * N_MEO + (n23 - N_AQI)) * 64;
                        *reinterpret_cast<float2*>(dst + col) = make_float2(s2, s3);
                    }
                }
            }
        }
    }
}

extern "C" void kernel_launch(void* const* d_in, const int* in_sizes, int n_in,
                              void* d_out, int out_size)
{
    const float* aqi_inp      = (const float*)d_in[0];
    const float* meo_inp      = (const float*)d_in[1];
    const float* context_feat = (const float*)d_in[2];
    const float* adj_norm     = (const float*)d_in[3];
    const float* aqi_idE      = (const float*)d_in[4];
    const float* aqi_monthE   = (const float*)d_in[5];
    const float* aqi_weekdayE = (const float*)d_in[6];
    const float* aqi_hourE    = (const float*)d_in[7];
    const float* meo_windE    = (const float*)d_in[8];
    const float* meo_idE      = (const float*)d_in[9];
    const float* meo_monthE   = (const float*)d_in[10];
    const float* meo_weekdayE = (const float*)d_in[11];
    const float* meo_hourE    = (const float*)d_in[12];
    const float* W_xa         = (const float*)d_in[13];
    const float* W_xm         = (const float*)d_in[14];
    const float* W_ua         = (const float*)d_in[15];
    const float* W_um         = (const float*)d_in[16];
    const float* a_aa         = (const float*)d_in[17];
    const float* a_am         = (const float*)d_in[18];
    const float* a_ma         = (const float*)d_in[19];
    const float* a_mm         = (const float*)d_in[20];
    const int*   aqi_ex       = (const int*)d_in[21];
    const int*   meo_ex       = (const int*)d_in[22];
    const int*   adj          = (const int*)d_in[23];
    float* out = (float*)d_out;

    precompute_kernel<<<1, 256>>>(context_feat, adj_norm,
                                  a_aa, a_am, a_ma, a_mm,
                                  W_ua, W_um, W_xa, W_xm, adj);
    hgat_kernel<<<BATCH, 256>>>(aqi_inp, meo_inp,
                                aqi_idE, aqi_monthE, aqi_weekdayE, aqi_hourE,
                                meo_windE, meo_idE, meo_monthE, meo_weekdayE, meo_hourE,
                                aqi_ex, meo_ex, out);
}

// round 9
// speedup vs baseline: 1.3248x; 1.1769x over previous
#include <cuda_runtime.h>
#include <cuda_fp16.h>
#include <cstddef>
#include <cstdint>

#define N_AQI 35
#define N_MEO 18
#define NTOT  53
#define F_OUT 64
#define CTXD  60
#define BATCH 4096
#define NEGV  (-1e12f)
#define LALPHA 0.2f

#define WT_STRIDE  20
#define FULL_STRIDE 28
#define PRE_BLOCKS 16

// K-column permutation: col c -> node j. MEO first (even-aligned pairs everywhere).
//   c in [0,18)  -> j = 35 + c   (MEO)
//   c in [18,53) -> j = c - 18   (AQI)

// ---------------- batch-independent precomputed state ----------------
__device__ __align__(16) float g_biasP[NTOT * 56];
__device__ __align__(16) unsigned long long g_maskP[NTOT];
__device__ __align__(16) float g_wsrc[2][2][FULL_STRIDE];
__device__ __align__(16) float g_wdst[2][2][FULL_STRIDE];
__device__ __align__(16) float g_WxaT[64 * WT_STRIDE];
__device__ __align__(16) float g_WxmT[64 * WT_STRIDE];

__global__ void precompute_kernel(
    const float* __restrict__ ctx,
    const float* __restrict__ adj_norm,
    const float* __restrict__ a_aa, const float* __restrict__ a_am,
    const float* __restrict__ a_ma, const float* __restrict__ a_mm,
    const float* __restrict__ W_ua, const float* __restrict__ W_um,
    const float* __restrict__ W_xa, const float* __restrict__ W_xm,
    const int*   __restrict__ adj)
{
    __shared__ float s_cs[NTOT][2];
    __shared__ float s_ct[NTOT][2];
    const int tid = threadIdx.x;
    const int gid = blockIdx.x * 256 + tid;
    const int gstr = PRE_BLOCKS * 256;
    const float* A[2][2] = {{a_aa, a_am}, {a_ma, a_mm}};

    // every block computes s_cs / s_ct (redundant, cheap)
    for (int id = tid; id < NTOT * 4; id += 256) {
        int i = id % NTOT;
        int sel = id / NTOT;
        if (sel < 2) {
            int rb = (i < N_AQI) ? 0 : 1;
            const float* a = A[rb][sel];
            float acc = 0.f;
            for (int c = 0; c < CTXD; c++) acc += ctx[i * CTXD + c] * a[64 + c];
            s_cs[i][sel] = acc;
        } else {
            int rb = sel - 2;
            int cb = (i < N_AQI) ? 0 : 1;
            const float* a = A[rb][cb];
            float acc = 0.f;
            for (int c = 0; c < CTXD; c++) acc += ctx[i * CTXD + c] * a[188 + c];
            s_ct[i][rb] = acc;
        }
    }

    // grid-strided independent outputs
    for (int id = gid; id < 2 * 2 * 2 * FULL_STRIDE; id += gstr) {
        int k = id % FULL_STRIDE;
        int r = id / FULL_STRIDE;
        int which = r >> 2;
        int t0 = (r >> 1) & 1;
        int t1 = r & 1;
        const float* W = (t0 == 0) ? W_ua : W_um;
        int K = (t0 == 0) ? 24 : 26;
        float acc = 0.f;
        if (k < K) {
            const float* a = (which == 0) ? A[t0][t1] : A[t1][t0];
            int off = (which == 0) ? 0 : 124;
            for (int f = 0; f < 64; f++) acc += W[k * 64 + f] * a[off + f];
        }
        if (which == 0) g_wsrc[t0][t1][k] = acc;
        else            g_wdst[t0][t1][k] = acc;
    }

    for (int id = gid; id < 64 * WT_STRIDE; id += gstr) {
        int f = id / WT_STRIDE, k = id % WT_STRIDE;
        g_WxaT[id] = (k < 16) ? W_xa[k * 64 + f] : 0.f;
        g_WxmT[id] = (k < 16) ? W_xm[k * 64 + f] : 0.f;
    }

    for (int i = gid; i < NTOT; i += gstr) {
        unsigned long long m = 0ull;
        for (int c = 0; c < NTOT; c++) {
            int j = (c < 18) ? 35 + c : c - 18;
            if (adj[i * NTOT + j] > 0) m |= (1ull << c);
        }
        g_maskP[i] = m;
    }
    __syncthreads();

    for (int id = gid; id < NTOT * 56; id += gstr) {
        int i = id / 56, c = id % 56;
        float v = 0.f;
        if (c < NTOT) {
            int j = (c < 18) ? 35 + c : c - 18;
            int rb = (i < N_AQI) ? 0 : 1;
            int cb = (j < N_AQI) ? 0 : 1;
            v = s_cs[i][cb] + s_ct[j][rb] + adj_norm[i * NTOT + j] * A[rb][cb][248];
        }
        g_biasP[id] = v;
    }
}

// ---------------- helpers ----------------
__device__ __forceinline__ unsigned long long fma2(unsigned long long a,
                                                   unsigned long long b,
                                                   unsigned long long c)
{
    unsigned long long d;
    asm("fma.rn.f32x2 %0, %1, %2, %3;" : "=l"(d) : "l"(a), "l"(b), "l"(c));
    return d;
}
__device__ __forceinline__ float lo32(unsigned long long v) { return __uint_as_float((unsigned)v); }
__device__ __forceinline__ float hi32(unsigned long long v) { return __uint_as_float((unsigned)(v >> 32)); }

__device__ __forceinline__ uint32_t smem_u32(const void* p) {
    uint32_t a;
    asm("{ .reg .u64 t; cvta.to.shared.u64 t, %1; cvt.u32.u64 %0, t; }" : "=r"(a) : "l"(p));
    return a;
}
__device__ __forceinline__ uint32_t pack2h(float a, float b) {
    __half2 v = __floats2half2_rn(a, b);    // a -> low halfword
    return *reinterpret_cast<uint32_t*>(&v);
}
__device__ __forceinline__ void ldmx4(uint32_t addr, uint32_t& r0, uint32_t& r1,
                                      uint32_t& r2, uint32_t& r3)
{
    asm volatile("ldmatrix.sync.aligned.m8n8.x4.shared.b16 {%0,%1,%2,%3}, [%4];"
                 : "=r"(r0), "=r"(r1), "=r"(r2), "=r"(r3) : "r"(addr));
}
__device__ __forceinline__ void mma16816(float* d, const uint32_t* a, uint32_t b0, uint32_t b1)
{
    asm volatile(
        "mma.sync.aligned.m16n8k16.row.col.f32.f16.f16.f32 "
        "{%0,%1,%2,%3}, {%4,%5,%6,%7}, {%8,%9}, {%0,%1,%2,%3};"
        : "+f"(d[0]), "+f"(d[1]), "+f"(d[2]), "+f"(d[3])
        : "r"(a[0]), "r"(a[1]), "r"(a[2]), "r"(a[3]), "r"(b0), "r"(b1));
}

// ---------------- main kernel: one CTA per batch element ----------------
__global__ __launch_bounds__(256, 4) void hgat_kernel(
    const float* __restrict__ aqi_inp, const float* __restrict__ meo_inp,
    const float* __restrict__ aqi_idE, const float* __restrict__ aqi_monthE,
    const float* __restrict__ aqi_weekdayE, const float* __restrict__ aqi_hourE,
    const float* __restrict__ meo_windE, const float* __restrict__ meo_idE,
    const float* __restrict__ meo_monthE, const float* __restrict__ meo_weekdayE,
    const float* __restrict__ meo_hourE,
    const int* __restrict__ aqi_ex, const int* __restrict__ meo_ex,
    float* __restrict__ out)
{
    // A: 64x64 fp16, 128B rows, SW-swizzled. Row i = attn[i] (permuted cols).
    // B: 64x64 fp16, 128B rows. Row f = pxT[f] (permuted cols).
    __shared__ __align__(1024) unsigned char s_A[64 * 128];
    __shared__ __align__(1024) unsigned char s_B[64 * 128];
    __shared__ __align__(16) float s_full[56 * FULL_STRIDE];
    __shared__ __align__(16) float s_S[NTOT * 2];
    __shared__ __align__(16) float s_T[54 * 2];   // permuted-col index, col 53 zeroed

    const int tid = threadIdx.x;
    const int wid = tid >> 5;
    const int lane = tid & 31;
    const int b = blockIdx.x;

    // ---- Phase 0: K-pad zeroing, feature copy, embedding gather ----
    {
        const float4 z4 = make_float4(0.f, 0.f, 0.f, 0.f);
        // zero logical bytes [96,128) (cols 48-63) of every tile row; cols 48-52
        // get overwritten by phases 1/3 after the barrier.
        if (tid < 128) {
            int row = tid & 63;
            unsigned char* base = (tid < 64) ? s_A : s_B;
            uint32_t sw = (uint32_t)((row & 7) << 4);
            *reinterpret_cast<float4*>(base + row * 128 + (96u ^ sw)) = z4;
            *reinterpret_cast<float4*>(base + row * 128 + (112u ^ sw)) = z4;
        }
        // input features: 53 rows x 4 float4
        if (tid < NTOT * 4) {
            int row = tid >> 2, q = tid & 3;
            float4 v = (row < N_AQI)
                ? *reinterpret_cast<const float4*>(&aqi_inp[((size_t)b * N_AQI + row) * 16 + 4 * q])
                : *reinterpret_cast<const float4*>(&meo_inp[((size_t)b * N_MEO + (row - N_AQI)) * 16 + 4 * q]);
            *reinterpret_cast<float4*>(&s_full[row * FULL_STRIDE + 4 * q]) = v;
        }
        // AQI embeddings: 35 rows x 4 slots (float2 each)
        for (int id = tid; id < N_AQI * 4; id += 256) {
            int row = id >> 2, e = id & 3;
            int ix = aqi_ex[((size_t)b * N_AQI + row) * 4 + e];
            const float* tab = (e == 0) ? aqi_idE : (e == 1) ? aqi_monthE
                             : (e == 2) ? aqi_weekdayE : aqi_hourE;
            *reinterpret_cast<float2*>(&s_full[row * FULL_STRIDE + 16 + 2 * e]) =
                *reinterpret_cast<const float2*>(&tab[ix * 2]);
        }
        // MEO embeddings: 18 rows x 5 slots
        for (int id = tid; id < N_MEO * 5; id += 256) {
            int row = id / 5, e = id - row * 5;
            int ix = meo_ex[((size_t)b * N_MEO + row) * 5 + e];
            const float* tab = (e == 0) ? meo_windE : (e == 1) ? meo_idE
                             : (e == 2) ? meo_monthE : (e == 3) ? meo_weekdayE : meo_hourE;
            *reinterpret_cast<float2*>(&s_full[(N_AQI + row) * FULL_STRIDE + 16 + 2 * e]) =
                *reinterpret_cast<const float2*>(&tab[ix * 2]);
        }
        // s_full pads: AQI cols 24-27, MEO cols 26-27; s_T col 53
        if (tid < N_AQI) {
            *reinterpret_cast<float4*>(&s_full[tid * FULL_STRIDE + 24]) = z4;
        } else if (tid < NTOT) {
            s_full[tid * FULL_STRIDE + 26] = 0.f;
            s_full[tid * FULL_STRIDE + 27] = 0.f;
        } else if (tid < NTOT + 2) {
            s_T[53 * 2 + (tid - NTOT)] = 0.f;
        }
    }
    __syncthreads();

    // ---- Phase 1: projxT -> fp16 pairs into B tile (permuted cols) ----
    {
        const int f = tid >> 2, rg = tid & 3;
        const uint32_t sw = (uint32_t)((f & 7) << 4);
        unsigned char* rowB = s_B + f * 128;

        // MEO pass: pairs at c0 = 2rg + 8r (c0 < 18), node j0 = 35 + c0
        {
            const float* wt = g_WxmT + f * WT_STRIDE;
            unsigned long long acc[3][2];
            #pragma unroll
            for (int r = 0; r < 3; r++) { acc[r][0] = 0ull; acc[r][1] = 0ull; }
            #pragma unroll
            for (int kg = 0; kg < 4; kg++) {
                ulonglong2 wv = *reinterpret_cast<const ulonglong2*>(wt + 4 * kg);
                #pragma unroll
                for (int r = 0; r < 3; r++) {
                    int c0 = 2 * rg + 8 * r;
                    if (c0 < 18) {
                        const float* x0 = &s_full[(N_AQI + c0) * FULL_STRIDE + 4 * kg];
                        ulonglong2 a0 = *reinterpret_cast<const ulonglong2*>(x0);
                        ulonglong2 a1 = *reinterpret_cast<const ulonglong2*>(x0 + FULL_STRIDE);
                        acc[r][0] = fma2(wv.x, a0.x, acc[r][0]);
                        acc[r][0] = fma2(wv.y, a0.y, acc[r][0]);
                        acc[r][1] = fma2(wv.x, a1.x, acc[r][1]);
                        acc[r][1] = fma2(wv.y, a1.y, acc[r][1]);
                    }
                }
            }
            #pragma unroll
            for (int r = 0; r < 3; r++) {
                int c0 = 2 * rg + 8 * r;
                if (c0 < 18) {
                    float p0 = lo32(acc[r][0]) + hi32(acc[r][0]);
                    float p1 = lo32(acc[r][1]) + hi32(acc[r][1]);
                    uint32_t off = ((uint32_t)(2 * c0)) ^ sw;
                    *reinterpret_cast<uint32_t*>(rowB + off) = pack2h(p0, p1);
                }
            }
        }
        // AQI pass: pairs at c0 = 18 + 2rg + 8r (c0 <= 52), node j0 = c0 - 18
        {
            const float* wt = g_WxaT + f * WT_STRIDE;
            unsigned long long acc[5][2];
            #pragma unroll
            for (int r = 0; r < 5; r++) { acc[r][0] = 0ull; acc[r][1] = 0ull; }
            #pragma unroll
            for (int kg = 0; kg < 4; kg++) {
                ulonglong2 wv = *reinterpret_cast<const ulonglong2*>(wt + 4 * kg);
                #pragma unroll
                for (int r = 0; r < 5; r++) {
                    int c0 = 18 + 2 * rg + 8 * r;
                    if (c0 <= 52) {
                        const float* x0 = &s_full[(c0 - 18) * FULL_STRIDE + 4 * kg];
                        ulonglong2 a0 = *reinterpret_cast<const ulonglong2*>(x0);
                        ulonglong2 a1 = *reinterpret_cast<const ulonglong2*>(x0 + FULL_STRIDE);
                        acc[r][0] = fma2(wv.x, a0.x, acc[r][0]);
                        acc[r][0] = fma2(wv.y, a0.y, acc[r][0]);
                        acc[r][1] = fma2(wv.x, a1.x, acc[r][1]);
                        acc[r][1] = fma2(wv.y, a1.y, acc[r][1]);
                    }
                }
            }
            #pragma unroll
            for (int r = 0; r < 5; r++) {
                int c0 = 18 + 2 * rg + 8 * r;
                if (c0 <= 52) {
                    float p0 = lo32(acc[r][0]) + hi32(acc[r][0]);
                    float p1 = (c0 == 52) ? 0.f : lo32(acc[r][1]) + hi32(acc[r][1]);
                    uint32_t off = ((uint32_t)(2 * c0)) ^ sw;
                    *reinterpret_cast<uint32_t*>(rowB + off) = pack2h(p0, p1);
                }
            }
        }
    }

    // ---- Phase 2: S[i][cb]; T -> permuted-col layout ----
    if (tid < NTOT * 4) {
        int i = tid % NTOT;
        int sel = tid / NTOT;
        int rt = (i < N_AQI) ? 0 : 1;
        const float4* xr = reinterpret_cast<const float4*>(&s_full[i * FULL_STRIDE]);
        const float4* wv = reinterpret_cast<const float4*>(
            (sel < 2) ? g_wsrc[rt][sel] : g_wdst[rt][sel - 2]);
        float acc = 0.f;
        #pragma unroll
        for (int m = 0; m < 7; m++) {
            float4 x = xr[m], w = wv[m];
            acc += x.x * w.x + x.y * w.y + x.z * w.z + x.w * w.w;
        }
        if (sel < 2) s_S[i * 2 + sel] = acc;
        else {
            int c = (i < N_AQI) ? i + 18 : i - N_AQI;
            s_T[c * 2 + (sel - 2)] = acc;
        }
    }
    __syncthreads();

    // ---- Phase 3: masked softmax -> packed fp16x2 into A tile (row i) ----
    {
        const bool act = (lane < 27);
        const int c0 = 2 * lane, c1 = c0 + 1;
        float4 tv = act ? *reinterpret_cast<const float4*>(&s_T[c0 * 2])
                        : make_float4(0.f, 0.f, 0.f, 0.f);
        const bool meo0 = (c0 < 18), meo1 = (c1 < 18);
        const uint32_t colOff = (uint32_t)(4 * lane);

        for (int i = wid; i < NTOT; i += 8) {
            const int rb = (i < N_AQI) ? 0 : 1;
            float e0 = -3.4e38f, e1 = -3.4e38f;
            if (act) {
                unsigned long long M = g_maskP[i];
                float2 sv = *reinterpret_cast<const float2*>(&s_S[i * 2]);
                float2 bp = *reinterpret_cast<const float2*>(&g_biasP[i * 56 + c0]);
                float s0 = meo0 ? sv.y : sv.x;
                float s1 = meo1 ? sv.y : sv.x;
                float t0 = rb ? tv.y : tv.x;
                float t1 = rb ? tv.w : tv.z;
                float v0 = s0 + t0 + bp.x; v0 = (v0 >= 0.f) ? v0 : LALPHA * v0;
                float v1 = s1 + t1 + bp.y; v1 = (v1 >= 0.f) ? v1 : LALPHA * v1;
                e0 = ((M >> c0) & 1ull) ? v0 : NEGV;
                e1 = ((M >> c1) & 1ull) ? v1 : NEGV;
                if (c1 >= NTOT) e1 = -3.4e38f;     // pad col excluded from softmax
            }
            float mx = fmaxf(e0, e1);
            #pragma unroll
            for (int o = 16; o > 0; o >>= 1) mx = fmaxf(mx, __shfl_xor_sync(0xffffffffu, mx, o));
            float p0 = act ? __expf(e0 - mx) : 0.f;
            float p1 = (act && c1 < NTOT) ? __expf(e1 - mx) : 0.f;
            float sum = p0 + p1;
            #pragma unroll
            for (int o = 16; o > 0; o >>= 1) sum += __shfl_xor_sync(0xffffffffu, sum, o);
            float inv = 1.f / sum;
            if (act) {
                uint32_t off = (uint32_t)(i * 128) + (colOff ^ ((uint32_t)(i & 7) << 4));
                *reinterpret_cast<uint32_t*>(s_A + off) = pack2h(p0 * inv, p1 * inv);
            }
        }
    }
    __syncthreads();

    // ---- Phase 4: D = A @ B^T via mma.sync m16n8k16 fp16 ----
    // warp = (mg: 32 rows) x (ng: 16 feats). 12 ldmatrix.x4 + 16 MMAs per warp.
    {
        const int mg = wid >> 2, ng = wid & 3;
        const int lm = lane >> 3, lr = lane & 7;
        const uint32_t aBase = smem_u32(s_A);
        const uint32_t bBase = smem_u32(s_B);
        const uint32_t swx = (uint32_t)(lr << 4);
        const uint32_t aCol = (uint32_t)((lm >> 1) << 4);
        const uint32_t bCol = (uint32_t)((lm & 1) << 4);

        uint32_t aRB[2], bRB;
        #pragma unroll
        for (int mt = 0; mt < 2; mt++) {
            int row = mg * 32 + mt * 16 + (lm & 1) * 8 + lr;
            aRB[mt] = aBase + (uint32_t)(row * 128);
        }
        {
            int row = ng * 16 + (lm >> 1) * 8 + lr;
            bRB = bBase + (uint32_t)(row * 128);
        }

        float d[2][2][4];
        #pragma unroll
        for (int mt = 0; mt < 2; mt++)
            #pragma unroll
            for (int nt = 0; nt < 2; nt++)
                #pragma unroll
                for (int q = 0; q < 4; q++) d[mt][nt][q] = 0.f;

        #pragma unroll
        for (int k = 0; k < 4; k++) {
            uint32_t a[2][4];
            #pragma unroll
            for (int mt = 0; mt < 2; mt++)
                ldmx4(aRB[mt] + (((uint32_t)(k << 5) + aCol) ^ swx),
                      a[mt][0], a[mt][1], a[mt][2], a[mt][3]);
            uint32_t b0, b1, b2, b3;
            ldmx4(bRB + (((uint32_t)(k << 5) + bCol) ^ swx), b0, b1, b2, b3);
            #pragma unroll
            for (int mt = 0; mt < 2; mt++) {
                mma16816(d[mt][0], a[mt], b0, b1);
                mma16816(d[mt][1], a[mt], b2, b3);
            }
        }

        // Epilogue: direct float2 stores (no pair-sum).
        const int r0l = lane >> 2;
        const int cl = (lane & 3) * 2;
        #pragma unroll
        for (int mt = 0; mt < 2; mt++) {
            #pragma unroll
            for (int nt = 0; nt < 2; nt++) {
                int r0 = mg * 32 + mt * 16 + r0l;
                int r1 = r0 + 8;
                int col = ng * 16 + nt * 8 + cl;
                if (r0 < NTOT) {
                    float* dst = (r0 < N_AQI)
                        ? out + ((size_t)b * N_AQI + r0) * 64
                        : out + (size_t)BATCH * N_AQI * 64 + ((size_t)b * N_MEO + (r0 - N_AQI)) * 64;
                    *reinterpret_cast<float2*>(dst + col) = make_float2(d[mt][nt][0], d[mt][nt][1]);
                }
                if (r1 < NTOT) {
                    float* dst = (r1 < N_AQI)
                        ? out + ((size_t)b * N_AQI + r1) * 64
                        : out + (size_t)BATCH * N_AQI * 64 + ((size_t)b * N_MEO + (r1 - N_AQI)) * 64;
                    *reinterpret_cast<float2*>(dst + col) = make_float2(d[mt][nt][2], d[mt][nt][3]);
                }
            }
        }
    }
}

extern "C" void kernel_launch(void* const* d_in, const int* in_sizes, int n_in,
                              void* d_out, int out_size)
{
    const float* aqi_inp      = (const float*)d_in[0];
    const float* meo_inp      = (const float*)d_in[1];
    const float* context_feat = (const float*)d_in[2];
    const float* adj_norm     = (const float*)d_in[3];
    const float* aqi_idE      = (const float*)d_in[4];
    const float* aqi_monthE   = (const float*)d_in[5];
    const float* aqi_weekdayE = (const float*)d_in[6];
    const float* aqi_hourE    = (const float*)d_in[7];
    const float* meo_windE    = (const float*)d_in[8];
    const float* meo_idE      = (const float*)d_in[9];
    const float* meo_monthE   = (const float*)d_in[10];
    const float* meo_weekdayE = (const float*)d_in[11];
    const float* meo_hourE    = (const float*)d_in[12];
    const float* W_xa         = (const float*)d_in[13];
    const float* W_xm         = (const float*)d_in[14];
    const float* W_ua         = (const float*)d_in[15];
    const float* W_um         = (const float*)d_in[16];
    const float* a_aa         = (const float*)d_in[17];
    const float* a_am         = (const float*)d_in[18];
    const float* a_ma         = (const float*)d_in[19];
    const float* a_mm         = (const float*)d_in[20];
    const int*   aqi_ex       = (const int*)d_in[21];
    const int*   meo_ex       = (const int*)d_in[22];
    const int*   adj          = (const int*)d_in[23];
    float* out = (float*)d_out;

    precompute_kernel<<<PRE_BLOCKS, 256>>>(context_feat, adj_norm,
                                           a_aa, a_am, a_ma, a_mm,
                                           W_ua, W_um, W_xa, W_xm, adj);
    hgat_kernel<<<BATCH, 256>>>(aqi_inp, meo_inp,
                                aqi_idE, aqi_monthE, aqi_weekdayE, aqi_hourE,
                                meo_windE, meo_idE, meo_monthE, meo_weekdayE, meo_hourE,
                                aqi_ex, meo_ex, out);
}

// round 10
// speedup vs baseline: 1.4205x; 1.0723x over previous
#include <cuda_runtime.h>
#include <cuda_fp16.h>
#include <cstddef>
#include <cstdint>

#define N_AQI 35
#define N_MEO 18
#define NTOT  53
#define F_OUT 64
#define CTXD  60
#define BATCH 4096
#define NEGV  (-1e12f)
#define LALPHA 0.2f

#define WT_STRIDE  20
#define FULL_STRIDE 28
#define PRE_BLOCKS 32

// K-column permutation: col c -> node j. MEO first (even-aligned pairs everywhere).
//   c in [0,18)  -> j = 35 + c   (MEO)
//   c in [18,53) -> j = c - 18   (AQI)

// ---------------- batch-independent precomputed state ----------------
__device__ __align__(16) float g_biasP[NTOT * 56];
__device__ __align__(16) unsigned long long g_maskP[NTOT];
__device__ __align__(16) float g_wsrc[2][2][FULL_STRIDE];
__device__ __align__(16) float g_wdst[2][2][FULL_STRIDE];
__device__ __align__(16) float g_WxaT[64 * WT_STRIDE];
__device__ __align__(16) float g_WxmT[64 * WT_STRIDE];

__global__ void precompute_kernel(
    const float* __restrict__ ctx,
    const float* __restrict__ adj_norm,
    const float* __restrict__ a_aa, const float* __restrict__ a_am,
    const float* __restrict__ a_ma, const float* __restrict__ a_mm,
    const float* __restrict__ W_ua, const float* __restrict__ W_um,
    const float* __restrict__ W_xa, const float* __restrict__ W_xm,
    const int*   __restrict__ adj)
{
    __shared__ float s_cs[NTOT][2];
    __shared__ float s_ct[NTOT][2];
    const int tid = threadIdx.x;
    const int gid = blockIdx.x * 256 + tid;
    const int gstr = PRE_BLOCKS * 256;
    const float* A[2][2] = {{a_aa, a_am}, {a_ma, a_mm}};

    for (int id = tid; id < NTOT * 4; id += 256) {
        int i = id % NTOT;
        int sel = id / NTOT;
        if (sel < 2) {
            int rb = (i < N_AQI) ? 0 : 1;
            const float* a = A[rb][sel];
            float acc = 0.f;
            for (int c = 0; c < CTXD; c++) acc += ctx[i * CTXD + c] * a[64 + c];
            s_cs[i][sel] = acc;
        } else {
            int rb = sel - 2;
            int cb = (i < N_AQI) ? 0 : 1;
            const float* a = A[rb][cb];
            float acc = 0.f;
            for (int c = 0; c < CTXD; c++) acc += ctx[i * CTXD + c] * a[188 + c];
            s_ct[i][rb] = acc;
        }
    }

    for (int id = gid; id < 2 * 2 * 2 * FULL_STRIDE; id += gstr) {
        int k = id % FULL_STRIDE;
        int r = id / FULL_STRIDE;
        int which = r >> 2;
        int t0 = (r >> 1) & 1;
        int t1 = r & 1;
        const float* W = (t0 == 0) ? W_ua : W_um;
        int K = (t0 == 0) ? 24 : 26;
        float acc = 0.f;
        if (k < K) {
            const float* a = (which == 0) ? A[t0][t1] : A[t1][t0];
            int off = (which == 0) ? 0 : 124;
            for (int f = 0; f < 64; f++) acc += W[k * 64 + f] * a[off + f];
        }
        if (which == 0) g_wsrc[t0][t1][k] = acc;
        else            g_wdst[t0][t1][k] = acc;
    }

    for (int id = gid; id < 64 * WT_STRIDE; id += gstr) {
        int f = id / WT_STRIDE, k = id % WT_STRIDE;
        g_WxaT[id] = (k < 16) ? W_xa[k * 64 + f] : 0.f;
        g_WxmT[id] = (k < 16) ? W_xm[k * 64 + f] : 0.f;
    }

    for (int i = gid; i < NTOT; i += gstr) {
        unsigned long long m = 0ull;
        for (int c = 0; c < NTOT; c++) {
            int j = (c < 18) ? 35 + c : c - 18;
            if (adj[i * NTOT + j] > 0) m |= (1ull << c);
        }
        g_maskP[i] = m;
    }
    __syncthreads();

    for (int id = gid; id < NTOT * 56; id += gstr) {
        int i = id / 56, c = id % 56;
        float v = 0.f;
        if (c < NTOT) {
            int j = (c < 18) ? 35 + c : c - 18;
            int rb = (i < N_AQI) ? 0 : 1;
            int cb = (j < N_AQI) ? 0 : 1;
            v = s_cs[i][cb] + s_ct[j][rb] + adj_norm[i * NTOT + j] * A[rb][cb][248];
        }
        g_biasP[id] = v;
    }
}

// ---------------- helpers ----------------
__device__ __forceinline__ unsigned long long fma2(unsigned long long a,
                                                   unsigned long long b,
                                                   unsigned long long c)
{
    unsigned long long d;
    asm("fma.rn.f32x2 %0, %1, %2, %3;" : "=l"(d) : "l"(a), "l"(b), "l"(c));
    return d;
}
__device__ __forceinline__ float lo32(unsigned long long v) { return __uint_as_float((unsigned)v); }
__device__ __forceinline__ float hi32(unsigned long long v) { return __uint_as_float((unsigned)(v >> 32)); }

__device__ __forceinline__ uint32_t smem_u32(const void* p) {
    uint32_t a;
    asm("{ .reg .u64 t; cvta.to.shared.u64 t, %1; cvt.u32.u64 %0, t; }" : "=r"(a) : "l"(p));
    return a;
}
__device__ __forceinline__ uint32_t pack2h(float a, float b) {
    __half2 v = __floats2half2_rn(a, b);    // a -> low halfword
    return *reinterpret_cast<uint32_t*>(&v);
}
__device__ __forceinline__ void ldmx4(uint32_t addr, uint32_t& r0, uint32_t& r1,
                                      uint32_t& r2, uint32_t& r3)
{
    asm volatile("ldmatrix.sync.aligned.m8n8.x4.shared.b16 {%0,%1,%2,%3}, [%4];"
                 : "=r"(r0), "=r"(r1), "=r"(r2), "=r"(r3) : "r"(addr));
}
__device__ __forceinline__ void mma16816(float* d, const uint32_t* a, uint32_t b0, uint32_t b1)
{
    asm volatile(
        "mma.sync.aligned.m16n8k16.row.col.f32.f16.f16.f32 "
        "{%0,%1,%2,%3}, {%4,%5,%6,%7}, {%8,%9}, {%0,%1,%2,%3};"
        : "+f"(d[0]), "+f"(d[1]), "+f"(d[2]), "+f"(d[3])
        : "r"(a[0]), "r"(a[1]), "r"(a[2]), "r"(a[3]), "r"(b0), "r"(b1));
}

// ---------------- main kernel: TWO batch elements per CTA ----------------
__global__ __launch_bounds__(256, 4) void hgat_kernel(
    const float* __restrict__ aqi_inp, const float* __restrict__ meo_inp,
    const float* __restrict__ aqi_idE, const float* __restrict__ aqi_monthE,
    const float* __restrict__ aqi_weekdayE, const float* __restrict__ aqi_hourE,
    const float* __restrict__ meo_windE, const float* __restrict__ meo_idE,
    const float* __restrict__ meo_monthE, const float* __restrict__ meo_weekdayE,
    const float* __restrict__ meo_hourE,
    const int* __restrict__ aqi_ex, const int* __restrict__ meo_ex,
    float* __restrict__ out)
{
    // Per batch e: A[e] 64x64 fp16 (attn, permuted cols), B[e] 64x64 fp16 (pxT).
    __shared__ __align__(1024) unsigned char s_A[2][64 * 128];
    __shared__ __align__(1024) unsigned char s_B[2][64 * 128];
    __shared__ __align__(16) float s_full[2][56 * FULL_STRIDE];
    __shared__ __align__(16) float s_S[2][108];
    __shared__ __align__(16) float s_T[2][108];   // permuted-col; col 53 zeroed

    const int tid = threadIdx.x;
    const int wid = tid >> 5;
    const int lane = tid & 31;
    const int b0 = blockIdx.x * 2;

    // ---- Phase 0: K-pad zeroing, feature copy, embedding gather (both batches) ----
    {
        const float4 z4 = make_float4(0.f, 0.f, 0.f, 0.f);
        // zero logical bytes [96,128) of every row of the 4 tiles
        {
            int t = tid >> 6, row = tid & 63;
            unsigned char* base = (t == 0) ? s_A[0] : (t == 1) ? s_A[1]
                                 : (t == 2) ? s_B[0] : s_B[1];
            uint32_t sw = (uint32_t)((row & 7) << 4);
            *reinterpret_cast<float4*>(base + row * 128 + (96u ^ sw)) = z4;
            *reinterpret_cast<float4*>(base + row * 128 + (112u ^ sw)) = z4;
        }
        // input features: 2 x 53 rows x 4 float4
        for (int id = tid; id < 2 * NTOT * 4; id += 256) {
            int e = id >= NTOT * 4;
            int id2 = id - e * NTOT * 4;
            int row = id2 >> 2, q = id2 & 3;
            int bb = b0 + e;
            float4 v = (row < N_AQI)
                ? *reinterpret_cast<const float4*>(&aqi_inp[((size_t)bb * N_AQI + row) * 16 + 4 * q])
                : *reinterpret_cast<const float4*>(&meo_inp[((size_t)bb * N_MEO + (row - N_AQI)) * 16 + 4 * q]);
            *reinterpret_cast<float4*>(&s_full[e][row * FULL_STRIDE + 4 * q]) = v;
        }
        // AQI embeddings: 2 x 35 rows x 4 slots
        for (int id = tid; id < 2 * N_AQI * 4; id += 256) {
            int e = id >= N_AQI * 4;
            int id2 = id - e * N_AQI * 4;
            int row = id2 >> 2, ee = id2 & 3;
            int ix = aqi_ex[((size_t)(b0 + e) * N_AQI + row) * 4 + ee];
            const float* tab = (ee == 0) ? aqi_idE : (ee == 1) ? aqi_monthE
                             : (ee == 2) ? aqi_weekdayE : aqi_hourE;
            *reinterpret_cast<float2*>(&s_full[e][row * FULL_STRIDE + 16 + 2 * ee]) =
                *reinterpret_cast<const float2*>(&tab[ix * 2]);
        }
        // MEO embeddings: 2 x 18 rows x 5 slots
        for (int id = tid; id < 2 * N_MEO * 5; id += 256) {
            int e = id >= N_MEO * 5;
            int id2 = id - e * N_MEO * 5;
            int row = id2 / 5, ee = id2 - row * 5;
            int ix = meo_ex[((size_t)(b0 + e) * N_MEO + row) * 5 + ee];
            const float* tab = (ee == 0) ? meo_windE : (ee == 1) ? meo_idE
                             : (ee == 2) ? meo_monthE : (ee == 3) ? meo_weekdayE : meo_hourE;
            *reinterpret_cast<float2*>(&s_full[e][(N_AQI + row) * FULL_STRIDE + 16 + 2 * ee]) =
                *reinterpret_cast<const float2*>(&tab[ix * 2]);
        }
        // pads
        if (tid < 2 * N_AQI) {
            int e = tid >= N_AQI, i = tid - e * N_AQI;
            *reinterpret_cast<float4*>(&s_full[e][i * FULL_STRIDE + 24]) = z4;
        } else if (tid < 2 * N_AQI + 2 * N_MEO) {
            int k = tid - 2 * N_AQI;
            int e = k >= N_MEO, i = N_AQI + k - e * N_MEO;
            s_full[e][i * FULL_STRIDE + 26] = 0.f;
            s_full[e][i * FULL_STRIDE + 27] = 0.f;
        } else if (tid < 2 * N_AQI + 2 * N_MEO + 4) {
            int k = tid - (2 * N_AQI + 2 * N_MEO);
            s_T[k >> 1][106 + (k & 1)] = 0.f;
        }
    }
    __syncthreads();

    // ---- Phase 1: projxT -> fp16 pairs into B tile (both batches) ----
    // thread: e = tid>>7, f = (tid>>1)&63, rg = tid&1
    {
        const int e = tid >> 7;
        const int f = (tid >> 1) & 63, rg = tid & 1;
        const uint32_t sw = (uint32_t)((f & 7) << 4);
        unsigned char* rowB = s_B[e] + f * 128;
        const float* full = s_full[e];

        // MEO pass: pair p = rg + 2r, p < 9; c0 = 2p, nodes 35+c0, 36+c0
        {
            const float* wt = g_WxmT + f * WT_STRIDE;
            unsigned long long acc[5][2];
            #pragma unroll
            for (int r = 0; r < 5; r++) { acc[r][0] = 0ull; acc[r][1] = 0ull; }
            #pragma unroll
            for (int kg = 0; kg < 4; kg++) {
                ulonglong2 wv = *reinterpret_cast<const ulonglong2*>(wt + 4 * kg);
                #pragma unroll
                for (int r = 0; r < 5; r++) {
                    int p = rg + 2 * r;
                    if (p < 9) {
                        const float* x0 = &full[(N_AQI + 2 * p) * FULL_STRIDE + 4 * kg];
                        ulonglong2 a0 = *reinterpret_cast<const ulonglong2*>(x0);
                        ulonglong2 a1 = *reinterpret_cast<const ulonglong2*>(x0 + FULL_STRIDE);
                        acc[r][0] = fma2(wv.x, a0.x, acc[r][0]);
                        acc[r][0] = fma2(wv.y, a0.y, acc[r][0]);
                        acc[r][1] = fma2(wv.x, a1.x, acc[r][1]);
                        acc[r][1] = fma2(wv.y, a1.y, acc[r][1]);
                    }
                }
            }
            #pragma unroll
            for (int r = 0; r < 5; r++) {
                int p = rg + 2 * r;
                if (p < 9) {
                    float p0 = lo32(acc[r][0]) + hi32(acc[r][0]);
                    float p1 = lo32(acc[r][1]) + hi32(acc[r][1]);
                    uint32_t off = ((uint32_t)(4 * p)) ^ sw;
                    *reinterpret_cast<uint32_t*>(rowB + off) = pack2h(p0, p1);
                }
            }
        }
        // AQI pass: pair p = 9 + rg + 2r, p < 27; c0 = 2p, nodes c0-18, c0-17
        {
            const float* wt = g_WxaT + f * WT_STRIDE;
            unsigned long long acc[9][2];
            #pragma unroll
            for (int r = 0; r < 9; r++) { acc[r][0] = 0ull; acc[r][1] = 0ull; }
            #pragma unroll
            for (int kg = 0; kg < 4; kg++) {
                ulonglong2 wv = *reinterpret_cast<const ulonglong2*>(wt + 4 * kg);
                #pragma unroll
                for (int r = 0; r < 9; r++) {
                    int p = 9 + rg + 2 * r;
                    if (p < 27) {
                        const float* x0 = &full[(2 * p - 18) * FULL_STRIDE + 4 * kg];
                        ulonglong2 a0 = *reinterpret_cast<const ulonglong2*>(x0);
                        ulonglong2 a1 = *reinterpret_cast<const ulonglong2*>(x0 + FULL_STRIDE);
                        acc[r][0] = fma2(wv.x, a0.x, acc[r][0]);
                        acc[r][0] = fma2(wv.y, a0.y, acc[r][0]);
                        acc[r][1] = fma2(wv.x, a1.x, acc[r][1]);
                        acc[r][1] = fma2(wv.y, a1.y, acc[r][1]);
                    }
                }
            }
            #pragma unroll
            for (int r = 0; r < 9; r++) {
                int p = 9 + rg + 2 * r;
                if (p < 27) {
                    float p0 = lo32(acc[r][0]) + hi32(acc[r][0]);
                    float p1 = (p == 26) ? 0.f : lo32(acc[r][1]) + hi32(acc[r][1]);
                    uint32_t off = ((uint32_t)(4 * p)) ^ sw;
                    *reinterpret_cast<uint32_t*>(rowB + off) = pack2h(p0, p1);
                }
            }
        }
    }

    // ---- Phase 2: S[i][cb]; T -> permuted-col layout (both batches) ----
    for (int id = tid; id < 2 * NTOT * 4; id += 256) {
        int e = id >= NTOT * 4;
        int id2 = id - e * NTOT * 4;
        int i = id2 % NTOT;
        int sel = id2 / NTOT;
        int rt = (i < N_AQI) ? 0 : 1;
        const float4* xr = reinterpret_cast<const float4*>(&s_full[e][i * FULL_STRIDE]);
        const float4* wv = reinterpret_cast<const float4*>(
            (sel < 2) ? g_wsrc[rt][sel] : g_wdst[rt][sel - 2]);
        float acc = 0.f;
        #pragma unroll
        for (int m = 0; m < 7; m++) {
            float4 x = xr[m], w = wv[m];
            acc += x.x * w.x + x.y * w.y + x.z * w.z + x.w * w.w;
        }
        if (sel < 2) s_S[e][i * 2 + sel] = acc;
        else {
            int c = (i < N_AQI) ? i + 18 : i - N_AQI;
            s_T[e][c * 2 + (sel - 2)] = acc;
        }
    }
    __syncthreads();

    // ---- Phase 3: masked softmax -> packed fp16x2 into A tile (both batches) ----
    // warps 0-3: batch 0 rows {w,w+4,...}; warps 4-7: batch 1.
    {
        const int e = wid >> 2, w4 = wid & 3;
        const bool act = (lane < 27);
        const int c0 = 2 * lane, c1 = c0 + 1;
        float4 tv = act ? *reinterpret_cast<const float4*>(&s_T[e][c0 * 2])
                        : make_float4(0.f, 0.f, 0.f, 0.f);
        const bool meo0 = (c0 < 18), meo1 = (c1 < 18);
        const uint32_t colOff = (uint32_t)(4 * lane);
        unsigned char* tileA = s_A[e];

        for (int i = w4; i < NTOT; i += 4) {
            const int rb = (i < N_AQI) ? 0 : 1;
            float e0 = -3.4e38f, e1 = -3.4e38f;
            if (act) {
                unsigned long long M = g_maskP[i];
                float2 sv = *reinterpret_cast<const float2*>(&s_S[e][i * 2]);
                float2 bp = *reinterpret_cast<const float2*>(&g_biasP[i * 56 + c0]);
                float s0 = meo0 ? sv.y : sv.x;
                float s1 = meo1 ? sv.y : sv.x;
                float t0 = rb ? tv.y : tv.x;
                float t1 = rb ? tv.w : tv.z;
                float v0 = s0 + t0 + bp.x; v0 = (v0 >= 0.f) ? v0 : LALPHA * v0;
                float v1 = s1 + t1 + bp.y; v1 = (v1 >= 0.f) ? v1 : LALPHA * v1;
                e0 = ((M >> c0) & 1ull) ? v0 : NEGV;
                e1 = ((M >> c1) & 1ull) ? v1 : NEGV;
                if (c1 >= NTOT) e1 = -3.4e38f;
            }
            float mx = fmaxf(e0, e1);
            #pragma unroll
            for (int o = 16; o > 0; o >>= 1) mx = fmaxf(mx, __shfl_xor_sync(0xffffffffu, mx, o));
            float p0 = act ? __expf(e0 - mx) : 0.f;
            float p1 = (act && c1 < NTOT) ? __expf(e1 - mx) : 0.f;
            float sum = p0 + p1;
            #pragma unroll
            for (int o = 16; o > 0; o >>= 1) sum += __shfl_xor_sync(0xffffffffu, sum, o);
            float inv = 1.f / sum;
            if (act) {
                uint32_t off = (uint32_t)(i * 128) + (colOff ^ ((uint32_t)(i & 7) << 4));
                *reinterpret_cast<uint32_t*>(tileA + off) = pack2h(p0 * inv, p1 * inv);
            }
        }
    }
    __syncthreads();

    // ---- Phase 4: D = A @ B^T via mma.sync m16n8k16 fp16 ----
    // warp: e = wid>>2; within batch: mg = (wid>>1)&1 (32 rows), ng = wid&1 (32 cols).
    // 16 ldmatrix.x4 + 32 MMAs per warp; B fragments reused across 2 m-tiles.
    {
        const int e = wid >> 2;
        const int mg = (wid >> 1) & 1, ng = wid & 1;
        const int lm = lane >> 3, lr = lane & 7;
        const uint32_t aBase = smem_u32(s_A[e]);
        const uint32_t bBase = smem_u32(s_B[e]);
        const uint32_t swx = (uint32_t)(lr << 4);
        const uint32_t aCol = (uint32_t)((lm >> 1) << 4);
        const uint32_t bCol = (uint32_t)((lm & 1) << 4);
        const int bb = b0 + e;

        uint32_t aRB[2], bRB[2];
        #pragma unroll
        for (int mt = 0; mt < 2; mt++) {
            int row = mg * 32 + mt * 16 + (lm & 1) * 8 + lr;
            aRB[mt] = aBase + (uint32_t)(row * 128);
        }
        #pragma unroll
        for (int ntp = 0; ntp < 2; ntp++) {
            int row = ng * 32 + ntp * 16 + (lm >> 1) * 8 + lr;
            bRB[ntp] = bBase + (uint32_t)(row * 128);
        }

        float d[2][4][4];
        #pragma unroll
        for (int mt = 0; mt < 2; mt++)
            #pragma unroll
            for (int nt = 0; nt < 4; nt++)
                #pragma unroll
                for (int q = 0; q < 4; q++) d[mt][nt][q] = 0.f;

        #pragma unroll
        for (int k = 0; k < 4; k++) {
            uint32_t a[2][4];
            #pragma unroll
            for (int mt = 0; mt < 2; mt++)
                ldmx4(aRB[mt] + (((uint32_t)(k << 5) + aCol) ^ swx),
                      a[mt][0], a[mt][1], a[mt][2], a[mt][3]);
            #pragma unroll
            for (int ntp = 0; ntp < 2; ntp++) {
                uint32_t b0r, b1r, b2r, b3r;
                ldmx4(bRB[ntp] + (((uint32_t)(k << 5) + bCol) ^ swx), b0r, b1r, b2r, b3r);
                #pragma unroll
                for (int mt = 0; mt < 2; mt++) {
                    mma16816(d[mt][ntp * 2 + 0], a[mt], b0r, b1r);
                    mma16816(d[mt][ntp * 2 + 1], a[mt], b2r, b3r);
                }
            }
        }

        // Epilogue: direct float2 stores.
        const int r0l = lane >> 2;
        const int cl = (lane & 3) * 2;
        #pragma unroll
        for (int mt = 0; mt < 2; mt++) {
            #pragma unroll
            for (int nt = 0; nt < 4; nt++) {
                int r0 = mg * 32 + mt * 16 + r0l;
                int r1 = r0 + 8;
                int col = ng * 32 + nt * 8 + cl;
                if (r0 < NTOT) {
                    float* dst = (r0 < N_AQI)
                        ? out + ((size_t)bb * N_AQI + r0) * 64
                        : out + (size_t)BATCH * N_AQI * 64 + ((size_t)bb * N_MEO + (r0 - N_AQI)) * 64;
                    *reinterpret_cast<float2*>(dst + col) = make_float2(d[mt][nt][0], d[mt][nt][1]);
                }
                if (r1 < NTOT) {
                    float* dst = (r1 < N_AQI)
                        ? out + ((size_t)bb * N_AQI + r1) * 64
                        : out + (size_t)BATCH * N_AQI * 64 + ((size_t)bb * N_MEO + (r1 - N_AQI)) * 64;
                    *reinterpret_cast<float2*>(dst + col) = make_float2(d[mt][nt][2], d[mt][nt][3]);
                }
            }
        }
    }
}

extern "C" void kernel_launch(void* const* d_in, const int* in_sizes, int n_in,
                              void* d_out, int out_size)
{
    const float* aqi_inp      = (const float*)d_in[0];
    const float* meo_inp      = (const float*)d_in[1];
    const float* context_feat = (const float*)d_in[2];
    const float* adj_norm     = (const float*)d_in[3];
    const float* aqi_idE      = (const float*)d_in[4];
    const float* aqi_monthE   = (const float*)d_in[5];
    const float* aqi_weekdayE = (const float*)d_in[6];
    const float* aqi_hourE    = (const float*)d_in[7];
    const float* meo_windE    = (const float*)d_in[8];
    const float* meo_idE      = (const float*)d_in[9];
    const float* meo_monthE   = (const float*)d_in[10];
    const float* meo_weekdayE = (const float*)d_in[11];
    const float* meo_hourE    = (const float*)d_in[12];
    const float* W_xa         = (const float*)d_in[13];
    const float* W_xm         = (const float*)d_in[14];
    const float* W_ua         = (const float*)d_in[15];
    const float* W_um         = (const float*)d_in[16];
    const float* a_aa         = (const float*)d_in[17];
    const float* a_am         = (const float*)d_in[18];
    const float* a_ma         = (const float*)d_in[19];
    const float* a_mm         = (const float*)d_in[20];
    const int*   aqi_ex       = (const int*)d_in[21];
    const int*   meo_ex       = (const int*)d_in[22];
    const int*   adj          = (const int*)d_in[23];
    float* out = (float*)d_out;

    precompute_kernel<<<PRE_BLOCKS, 256>>>(context_feat, adj_norm,
                                           a_aa, a_am, a_ma, a_mm,
                                           W_ua, W_um, W_xa, W_xm, adj);
    hgat_kernel<<<BATCH / 2, 256>>>(aqi_inp, meo_inp,
                                    aqi_idE, aqi_monthE, aqi_weekdayE, aqi_hourE,
                                    meo_windE, meo_idE, meo_monthE, meo_weekdayE, meo_hourE,
                                    aqi_ex, meo_ex, out);
}